// round 6
// baseline (speedup 1.0000x reference)
#include <cuda_runtime.h>
#include <cuda_bf16.h>
#include <math.h>
#include <stdint.h>

// ---------------------------------------------------------------------------
// Problem constants
// ---------------------------------------------------------------------------
#define N_ROI   1000
#define M_PAD   1024
#define FH      38
#define FW      50
#define FCH     512
#define CROP    14
#define POOL    7
#define DFLAT   25088
#define DHID    4096
#define NCLS    21
#define NREG    80

// ---------------------------------------------------------------------------
// Scratch (device globals — no allocation allowed)
// ---------------------------------------------------------------------------
__device__ __nv_bfloat16 g_x0h[(size_t)M_PAD * DFLAT];
__device__ __nv_bfloat16 g_x0l[(size_t)M_PAD * DFLAT];
__device__ __nv_bfloat16 g_x1h[(size_t)M_PAD * DHID];
__device__ __nv_bfloat16 g_x1l[(size_t)M_PAD * DHID];
__device__ float         g_x2 [(size_t)M_PAD * DHID];
__device__ __nv_bfloat16 g_w1h[(size_t)DHID * DFLAT];
__device__ __nv_bfloat16 g_w1l[(size_t)DHID * DFLAT];
__device__ __nv_bfloat16 g_w2h[(size_t)DHID * DHID];
__device__ __nv_bfloat16 g_w2l[(size_t)DHID * DHID];

// ---------------------------------------------------------------------------
// asm helpers (compute_103-safe)
// ---------------------------------------------------------------------------
__device__ __forceinline__ uint32_t smem_u32(const void* p) {
    uint32_t a;
    asm("{ .reg .u64 t; cvta.to.shared.u64 t, %1; cvt.u32.u64 %0, t; }" : "=r"(a) : "l"(p));
    return a;
}
__device__ __forceinline__ void ldsm4(uint32_t r[4], uint32_t addr) {
    asm volatile("ldmatrix.sync.aligned.m8n8.x4.shared.b16 {%0,%1,%2,%3}, [%4];"
                 : "=r"(r[0]), "=r"(r[1]), "=r"(r[2]), "=r"(r[3]) : "r"(addr));
}
__device__ __forceinline__ void mma16816(float d[4], const uint32_t a[4],
                                         uint32_t b0, uint32_t b1) {
    asm volatile(
        "mma.sync.aligned.m16n8k16.row.col.f32.bf16.bf16.f32 "
        "{%0,%1,%2,%3}, {%4,%5,%6,%7}, {%8,%9}, {%0,%1,%2,%3};"
        : "+f"(d[0]), "+f"(d[1]), "+f"(d[2]), "+f"(d[3])
        : "r"(a[0]), "r"(a[1]), "r"(a[2]), "r"(a[3]), "r"(b0), "r"(b1));
}
#define CP_A16(dst, src) \
    asm volatile("cp.async.cg.shared.global [%0], [%1], 16;" :: "r"(dst), "l"(src))
#define CP_A16Z(dst, src, n) \
    asm volatile("cp.async.cg.shared.global [%0], [%1], 16, %2;" :: "r"(dst), "l"(src), "r"(n))
#define CP_COMMIT()      asm volatile("cp.async.commit_group;" ::: "memory")
#define CP_WAIT_GROUP(n) asm volatile("cp.async.wait_group %0;" :: "n"(n) : "memory")

__device__ __forceinline__ uint32_t pack2(__nv_bfloat16 a, __nv_bfloat16 b) {
    __nv_bfloat162 t; t.x = a; t.y = b;
    return *(uint32_t*)&t;
}

// ---------------------------------------------------------------------------
// Kernel 1: crop_and_resize + 2x2 maxpool, emits bf16 hi/lo split directly.
// ---------------------------------------------------------------------------
__global__ __launch_bounds__(128)
void roi_pool_kernel(const float* __restrict__ feats,
                     const float* __restrict__ props,
                     __nv_bfloat16* __restrict__ x0h,
                     __nv_bfloat16* __restrict__ x0l)
{
    const int n  = blockIdx.x;
    const int py = blockIdx.y;
    const int c4 = threadIdx.x;

    const float y1 = props[n*4 + 0];
    const float x1 = props[n*4 + 1];
    const float y2 = props[n*4 + 2];
    const float x2 = props[n*4 + 3];

    const float Hm1 = (float)(FH - 1);
    const float Wm1 = (float)(FW - 1);
    const float ystep = (y2 - y1) * Hm1 * (1.0f / (CROP - 1));
    const float xstep = (x2 - x1) * Wm1 * (1.0f / (CROP - 1));
    const float ybase = y1 * Hm1;
    const float xbase = x1 * Wm1;

    int   y0i[2], y1i[2];
    float wy[2];
    #pragma unroll
    for (int dy = 0; dy < 2; dy++) {
        float ys = ybase + (float)(2*py + dy) * ystep;
        float yf = floorf(ys);
        wy[dy] = ys - yf;
        int yi = (int)yf;
        if (yi < 0) yi = 0;
        if (yi > FH-1) yi = FH-1;
        y0i[dy] = yi;
        y1i[dy] = (yi + 1 < FH-1) ? (yi + 1) : (FH-1);
    }

    for (int px = 0; px < POOL; px++) {
        float4 mx = make_float4(-1e30f, -1e30f, -1e30f, -1e30f);
        #pragma unroll
        for (int dx = 0; dx < 2; dx++) {
            float xs = xbase + (float)(2*px + dx) * xstep;
            float xf = floorf(xs);
            float wx = xs - xf;
            int xi = (int)xf;
            if (xi < 0) xi = 0;
            if (xi > FW-1) xi = FW-1;
            int x0c = xi;
            int x1c = (xi + 1 < FW-1) ? (xi + 1) : (FW-1);
            #pragma unroll
            for (int dy = 0; dy < 2; dy++) {
                const float4* r0 = (const float4*)&feats[((size_t)y0i[dy]*FW)*FCH];
                const float4* r1 = (const float4*)&feats[((size_t)y1i[dy]*FW)*FCH];
                float4 v00 = r0[(size_t)x0c*(FCH/4) + c4];
                float4 v01 = r0[(size_t)x1c*(FCH/4) + c4];
                float4 v10 = r1[(size_t)x0c*(FCH/4) + c4];
                float4 v11 = r1[(size_t)x1c*(FCH/4) + c4];
                float w = wy[dy];
                float4 top, bot, val;
                top.x = v00.x + (v01.x - v00.x) * wx;
                top.y = v00.y + (v01.y - v00.y) * wx;
                top.z = v00.z + (v01.z - v00.z) * wx;
                top.w = v00.w + (v01.w - v00.w) * wx;
                bot.x = v10.x + (v11.x - v10.x) * wx;
                bot.y = v10.y + (v11.y - v10.y) * wx;
                bot.z = v10.z + (v11.z - v10.z) * wx;
                bot.w = v10.w + (v11.w - v10.w) * wx;
                val.x = top.x + (bot.x - top.x) * w;
                val.y = top.y + (bot.y - top.y) * w;
                val.z = top.z + (bot.z - top.z) * w;
                val.w = top.w + (bot.w - top.w) * w;
                mx.x = fmaxf(mx.x, val.x);
                mx.y = fmaxf(mx.y, val.y);
                mx.z = fmaxf(mx.z, val.z);
                mx.w = fmaxf(mx.w, val.w);
            }
        }
        const float* v = (const float*)&mx;
        __nv_bfloat16 h[4], l[4];
        #pragma unroll
        for (int e = 0; e < 4; e++) {
            h[e] = __float2bfloat16_rn(v[e]);
            l[e] = __float2bfloat16_rn(v[e] - __bfloat162float(h[e]));
        }
        size_t idx = (size_t)n*DFLAT + ((size_t)(py*POOL + px))*FCH + (size_t)c4*4;
        *(uint2*)&x0h[idx] = make_uint2(pack2(h[0],h[1]), pack2(h[2],h[3]));
        *(uint2*)&x0l[idx] = make_uint2(pack2(l[0],l[1]), pack2(l[2],l[3]));
    }
}

// ---------------------------------------------------------------------------
// Kernel 2: W [K,N] fp32 -> W^T hi/lo [N,K] bf16.
// ---------------------------------------------------------------------------
__global__ __launch_bounds__(256)
void convert_w_kernel(const float* __restrict__ W,
                      __nv_bfloat16* __restrict__ Th,
                      __nv_bfloat16* __restrict__ Tl,
                      int K, int N)
{
    __shared__ float ts[64][33];
    const int tx = threadIdx.x & 31;
    const int ty = threadIdx.x >> 5;
    const int kb = blockIdx.y * 64;
    const int nb = blockIdx.x * 32;

    #pragma unroll
    for (int j = 0; j < 8; j++) {
        int r = ty + j * 8;
        ts[r][tx] = W[(size_t)(kb + r) * N + nb + tx];
    }
    __syncthreads();

    #pragma unroll
    for (int j = 0; j < 4; j++) {
        int n = ty + j * 8;
        float a = ts[2*tx][n];
        float b = ts[2*tx + 1][n];
        __nv_bfloat16 ah = __float2bfloat16_rn(a);
        __nv_bfloat16 bh = __float2bfloat16_rn(b);
        __nv_bfloat16 al = __float2bfloat16_rn(a - __bfloat162float(ah));
        __nv_bfloat16 bl = __float2bfloat16_rn(b - __bfloat162float(bh));
        size_t o = (size_t)(nb + n) * K + kb + 2 * tx;
        *(uint32_t*)&Th[o] = pack2(ah, bh);
        *(uint32_t*)&Tl[o] = pack2(al, bl);
    }
}

// ---------------------------------------------------------------------------
// Kernel 3: HMMA bf16 3-product GEMM, pre-split operands, sweep-ordered MMAs.
// BM=256, BN=128, BK=32, 512 threads, warp tile 64x32, 3-stage cp.async.
// ---------------------------------------------------------------------------
#define PITCH  80
#define AH_OFF 0
#define AL_OFF 20480
#define BH_OFF 40960
#define BL_OFF 51200
#define STAGE  61440
#define NSTAGE 3
#define GEMM_SMEM (NSTAGE * STAGE)    // 184320 B

__global__ __launch_bounds__(512, 1)
void gemm_tc_kernel(const __nv_bfloat16* __restrict__ Ah,
                    const __nv_bfloat16* __restrict__ Al,
                    int m_real,
                    const __nv_bfloat16* __restrict__ Bh,
                    const __nv_bfloat16* __restrict__ Bl,
                    const float* __restrict__ bias,
                    float* __restrict__ Cf,
                    __nv_bfloat16* __restrict__ Ch,
                    __nv_bfloat16* __restrict__ Cl,
                    int K, int out_bf16)
{
    extern __shared__ char smem[];
    const uint32_t sb0 = smem_u32(smem);
    const int tid  = threadIdx.x;
    const int wid  = tid >> 5;
    const int lane = tid & 31;
    const int wm   = wid & 3;            // 0..3 (M groups of 64)
    const int wn   = wid >> 2;           // 0..3 (N groups of 32)
    const int bn = blockIdx.x, bm = blockIdx.y;
    const int nch = K >> 5;

    const uint32_t lm_off = (uint32_t)((lane & 15) * PITCH + (lane >> 4) * 16);

    // ---- load roles ----
    const int a_row  = tid >> 1;              // 0..255
    const int a_half = tid & 1;
    const int a_gm   = bm * 256 + a_row;
    const uint32_t a_fill = (a_gm < m_real) ? 16u : 0u;
    const int a_sr   = (a_gm < m_real) ? a_gm : (m_real - 1);
    const __nv_bfloat16* ah_src = Ah + (size_t)a_sr * K + a_half * 16;
    const __nv_bfloat16* al_src = Al + (size_t)a_sr * K + a_half * 16;
    const uint32_t a_dst = (uint32_t)(a_row * PITCH + a_half * 32);
    const int b_row = tid >> 2;               // 0..127
    const int b_ch  = tid & 3;
    const __nv_bfloat16* bh_src = Bh + (size_t)(bn * 128 + b_row) * K + b_ch * 8;
    const __nv_bfloat16* bl_src = Bl + (size_t)(bn * 128 + b_row) * K + b_ch * 8;
    const uint32_t b_dst = (uint32_t)(b_row * PITCH + b_ch * 16);

    float acc[4][4][4];
    #pragma unroll
    for (int i = 0; i < 4; i++)
        #pragma unroll
        for (int j = 0; j < 4; j++)
            #pragma unroll
            for (int e = 0; e < 4; e++) acc[i][j][e] = 0.0f;

    // ---- prologue: stages 0,1 ----
    #pragma unroll
    for (int s = 0; s < 2; s++) {
        const uint32_t st = sb0 + (uint32_t)s * STAGE;
        const int k0 = s * 32;
        CP_A16Z(st + AH_OFF + a_dst,      ah_src + k0,     a_fill);
        CP_A16Z(st + AH_OFF + a_dst + 16, ah_src + k0 + 8, a_fill);
        CP_A16Z(st + AL_OFF + a_dst,      al_src + k0,     a_fill);
        CP_A16Z(st + AL_OFF + a_dst + 16, al_src + k0 + 8, a_fill);
        CP_A16(st + BH_OFF + b_dst, bh_src + k0);
        CP_A16(st + BL_OFF + b_dst, bl_src + k0);
        CP_COMMIT();
    }

    for (int c = 0; c < nch; c++) {
        const uint32_t st = sb0 + (uint32_t)(c % NSTAGE) * STAGE;
        CP_WAIT_GROUP(1);
        __syncthreads();

        if (c + 2 < nch) {
            const uint32_t sn = sb0 + (uint32_t)((c + 2) % NSTAGE) * STAGE;
            const int k0 = (c + 2) * 32;
            CP_A16Z(sn + AH_OFF + a_dst,      ah_src + k0,     a_fill);
            CP_A16Z(sn + AH_OFF + a_dst + 16, ah_src + k0 + 8, a_fill);
            CP_A16Z(sn + AL_OFF + a_dst,      al_src + k0,     a_fill);
            CP_A16Z(sn + AL_OFF + a_dst + 16, al_src + k0 + 8, a_fill);
            CP_A16(sn + BH_OFF + b_dst, bh_src + k0);
            CP_A16(sn + BL_OFF + b_dst, bl_src + k0);
            CP_COMMIT();
        }

        #pragma unroll
        for (int kk = 0; kk < 2; kk++) {
            // ---- load ALL fragments for this k-slice (12 ldmatrix) ----
            uint32_t ah4[4][4], al4[4][4], qh[2][4], ql[2][4];
            #pragma unroll
            for (int nt2 = 0; nt2 < 2; nt2++) {
                uint32_t rb = st + BH_OFF +
                    (uint32_t)((wn*32 + nt2*16) * PITCH + kk*32) + lm_off;
                ldsm4(qh[nt2], rb);
                ldsm4(ql[nt2], rb + (BL_OFF - BH_OFF));
            }
            #pragma unroll
            for (int mt = 0; mt < 4; mt++) {
                uint32_t ra = st + AH_OFF +
                    (uint32_t)((wm*64 + mt*16) * PITCH + kk*32) + lm_off;
                ldsm4(ah4[mt], ra);
                ldsm4(al4[mt], ra + (AL_OFF - AH_OFF));
            }
            // ---- sweep 1: hi*hi (16 MMAs, all-independent accumulators) ----
            #pragma unroll
            for (int mt = 0; mt < 4; mt++)
                #pragma unroll
                for (int nt2 = 0; nt2 < 2; nt2++) {
                    mma16816(acc[mt][2*nt2],   ah4[mt], qh[nt2][0], qh[nt2][2]);
                    mma16816(acc[mt][2*nt2+1], ah4[mt], qh[nt2][1], qh[nt2][3]);
                }
            // ---- sweep 2: lo*hi ----
            #pragma unroll
            for (int mt = 0; mt < 4; mt++)
                #pragma unroll
                for (int nt2 = 0; nt2 < 2; nt2++) {
                    mma16816(acc[mt][2*nt2],   al4[mt], qh[nt2][0], qh[nt2][2]);
                    mma16816(acc[mt][2*nt2+1], al4[mt], qh[nt2][1], qh[nt2][3]);
                }
            // ---- sweep 3: hi*lo ----
            #pragma unroll
            for (int mt = 0; mt < 4; mt++)
                #pragma unroll
                for (int nt2 = 0; nt2 < 2; nt2++) {
                    mma16816(acc[mt][2*nt2],   ah4[mt], ql[nt2][0], ql[nt2][2]);
                    mma16816(acc[mt][2*nt2+1], ah4[mt], ql[nt2][1], ql[nt2][3]);
                }
        }
    }

    // ---- epilogue: bias + relu ----
    #pragma unroll
    for (int mt = 0; mt < 4; mt++) {
        const int row0 = bm*256 + wm*64 + mt*16 + (lane >> 2);
        #pragma unroll
        for (int nt = 0; nt < 4; nt++) {
            const int gn = bn*128 + wn*32 + nt*8 + 2*(lane & 3);
            const float b0 = bias[gn], b1 = bias[gn+1];
            float v00 = fmaxf(acc[mt][nt][0] + b0, 0.f);
            float v01 = fmaxf(acc[mt][nt][1] + b1, 0.f);
            float v10 = fmaxf(acc[mt][nt][2] + b0, 0.f);
            float v11 = fmaxf(acc[mt][nt][3] + b1, 0.f);
            if (out_bf16) {
                __nv_bfloat16 h00 = __float2bfloat16_rn(v00);
                __nv_bfloat16 h01 = __float2bfloat16_rn(v01);
                __nv_bfloat16 h10 = __float2bfloat16_rn(v10);
                __nv_bfloat16 h11 = __float2bfloat16_rn(v11);
                __nv_bfloat16 l00 = __float2bfloat16_rn(v00 - __bfloat162float(h00));
                __nv_bfloat16 l01 = __float2bfloat16_rn(v01 - __bfloat162float(h01));
                __nv_bfloat16 l10 = __float2bfloat16_rn(v10 - __bfloat162float(h10));
                __nv_bfloat16 l11 = __float2bfloat16_rn(v11 - __bfloat162float(h11));
                *(uint32_t*)&Ch[(size_t)row0 * DHID + gn]     = pack2(h00, h01);
                *(uint32_t*)&Cl[(size_t)row0 * DHID + gn]     = pack2(l00, l01);
                *(uint32_t*)&Ch[(size_t)(row0+8) * DHID + gn] = pack2(h10, h11);
                *(uint32_t*)&Cl[(size_t)(row0+8) * DHID + gn] = pack2(l10, l11);
            } else {
                *(float2*)&Cf[(size_t)row0 * DHID + gn]     = make_float2(v00, v01);
                *(float2*)&Cf[(size_t)(row0+8) * DHID + gn] = make_float2(v10, v11);
            }
        }
    }
}

// ---------------------------------------------------------------------------
// Kernel 4: heads, 8 ROIs per block.
// ---------------------------------------------------------------------------
#define HEAD_SMEM (8 * DHID * 4 + 8 * 32 * 4)

__global__ __launch_bounds__(128)
void head_kernel(const float* __restrict__ X,
                 const float* __restrict__ Wc, const float* __restrict__ bc,
                 const float* __restrict__ Wr, const float* __restrict__ br,
                 float* __restrict__ out)
{
    extern __shared__ float xs[];             // [4096][8]
    float* logits = xs + 8 * DHID;            // [8][32]
    const int b = blockIdx.x, t = threadIdx.x;

    for (int idx = t; idx < 8 * DHID; idx += 128) {
        int r = idx >> 12, k = idx & (DHID - 1);
        xs[k * 8 + r] = X[(size_t)(b * 8 + r) * DHID + k];
    }
    __syncthreads();

    if (t < NCLS + NREG) {
        const bool is_cls = (t < NCLS);
        const float* W = is_cls ? Wc : Wr;
        const int nc   = is_cls ? NCLS : NREG;
        const int j    = is_cls ? t : (t - NCLS);
        const float bv = is_cls ? bc[j] : br[j];
        float acc[8];
        #pragma unroll
        for (int r = 0; r < 8; r++) acc[r] = bv;
        #pragma unroll 4
        for (int k = 0; k < DHID; k++) {
            float w = W[(size_t)k * nc + j];
            float4 a = *(float4*)&xs[k * 8];
            float4 bq = *(float4*)&xs[k * 8 + 4];
            acc[0] = fmaf(a.x,  w, acc[0]);
            acc[1] = fmaf(a.y,  w, acc[1]);
            acc[2] = fmaf(a.z,  w, acc[2]);
            acc[3] = fmaf(a.w,  w, acc[3]);
            acc[4] = fmaf(bq.x, w, acc[4]);
            acc[5] = fmaf(bq.y, w, acc[5]);
            acc[6] = fmaf(bq.z, w, acc[6]);
            acc[7] = fmaf(bq.w, w, acc[7]);
        }
        if (is_cls) {
            #pragma unroll
            for (int r = 0; r < 8; r++) logits[r * 32 + j] = acc[r];
        } else {
            #pragma unroll
            for (int r = 0; r < 8; r++)
                out[(size_t)N_ROI * NCLS + (size_t)(b * 8 + r) * NREG + j] = acc[r];
        }
    }
    __syncthreads();

    if (t < 8) {
        int roi = b * 8 + t;
        float m = logits[t * 32];
        #pragma unroll
        for (int j = 1; j < NCLS; j++) m = fmaxf(m, logits[t * 32 + j]);
        float e[NCLS], s = 0.f;
        #pragma unroll
        for (int j = 0; j < NCLS; j++) { e[j] = expf(logits[t * 32 + j] - m); s += e[j]; }
        float inv = 1.0f / s;
        #pragma unroll
        for (int j = 0; j < NCLS; j++) out[(size_t)roi * NCLS + j] = e[j] * inv;
    }
}

// ---------------------------------------------------------------------------
// Launch
// ---------------------------------------------------------------------------
extern "C" void kernel_launch(void* const* d_in, const int* in_sizes, int n_in,
                              void* d_out, int out_size)
{
    const float* feats = (const float*)d_in[0];
    const float* props = (const float*)d_in[1];
    const float* W1    = (const float*)d_in[2];
    const float* b1    = (const float*)d_in[3];
    const float* W2    = (const float*)d_in[4];
    const float* b2    = (const float*)d_in[5];
    const float* Wc    = (const float*)d_in[6];
    const float* bc    = (const float*)d_in[7];
    const float* Wr    = (const float*)d_in[8];
    const float* br    = (const float*)d_in[9];
    float* out = (float*)d_out;

    __nv_bfloat16 *x0h, *x0l, *x1h, *x1l, *w1h, *w1l, *w2h, *w2l;
    float *x2;
    cudaGetSymbolAddress((void**)&x0h, g_x0h);
    cudaGetSymbolAddress((void**)&x0l, g_x0l);
    cudaGetSymbolAddress((void**)&x1h, g_x1h);
    cudaGetSymbolAddress((void**)&x1l, g_x1l);
    cudaGetSymbolAddress((void**)&x2,  g_x2);
    cudaGetSymbolAddress((void**)&w1h, g_w1h);
    cudaGetSymbolAddress((void**)&w1l, g_w1l);
    cudaGetSymbolAddress((void**)&w2h, g_w2h);
    cudaGetSymbolAddress((void**)&w2l, g_w2l);

    cudaFuncSetAttribute(gemm_tc_kernel, cudaFuncAttributeMaxDynamicSharedMemorySize, GEMM_SMEM);
    cudaFuncSetAttribute(head_kernel,    cudaFuncAttributeMaxDynamicSharedMemorySize, HEAD_SMEM);

    // 1. ROI crop_and_resize + maxpool -> x0 bf16 hi/lo
    roi_pool_kernel<<<dim3(N_ROI, POOL), 128>>>(feats, props, x0h, x0l);

    // 2. Weight convert+transpose -> bf16 hi/lo K-major
    convert_w_kernel<<<dim3(DHID / 32, DFLAT / 64), 256>>>(W1, w1h, w1l, DFLAT, DHID);
    convert_w_kernel<<<dim3(DHID / 32, DHID  / 64), 256>>>(W2, w2h, w2l, DHID,  DHID);

    // 3. FC1 -> x1 bf16 hi/lo
    gemm_tc_kernel<<<dim3(DHID / 128, M_PAD / 256), 512, GEMM_SMEM>>>(
        x0h, x0l, N_ROI, w1h, w1l, b1, nullptr, x1h, x1l, DFLAT, 1);

    // 4. FC2 -> x2 fp32
    gemm_tc_kernel<<<dim3(DHID / 128, M_PAD / 256), 512, GEMM_SMEM>>>(
        x1h, x1l, M_PAD, w2h, w2l, b2, x2, nullptr, nullptr, DHID, 0);

    // 5. Heads
    head_kernel<<<N_ROI / 8, 128, HEAD_SMEM>>>(x2, Wc, bc, Wr, br, out);
}

// round 9
// speedup vs baseline: 1.1695x; 1.1695x over previous
#include <cuda_runtime.h>
#include <cuda_bf16.h>
#include <math.h>
#include <stdint.h>

// ---------------------------------------------------------------------------
// Problem constants
// ---------------------------------------------------------------------------
#define N_ROI   1000
#define M_PAD   1024
#define FH      38
#define FW      50
#define FCH     512
#define CROP    14
#define POOL    7
#define DFLAT   25088
#define DHID    4096
#define NCLS    21
#define NREG    80

// ---------------------------------------------------------------------------
// Scratch (device globals — no allocation allowed)
// ---------------------------------------------------------------------------
__device__ __nv_bfloat16 g_x0h[(size_t)M_PAD * DFLAT];
__device__ __nv_bfloat16 g_x0l[(size_t)M_PAD * DFLAT];
__device__ __nv_bfloat16 g_x1h[(size_t)M_PAD * DHID];
__device__ __nv_bfloat16 g_x1l[(size_t)M_PAD * DHID];
__device__ float         g_x2 [(size_t)M_PAD * DHID];
__device__ __nv_bfloat16 g_w1h[(size_t)DHID * DFLAT];
__device__ __nv_bfloat16 g_w1l[(size_t)DHID * DFLAT];
__device__ __nv_bfloat16 g_w2h[(size_t)DHID * DHID];
__device__ __nv_bfloat16 g_w2l[(size_t)DHID * DHID];

// ---------------------------------------------------------------------------
// asm helpers (compute_103-safe)
// ---------------------------------------------------------------------------
__device__ __forceinline__ uint32_t smem_u32(const void* p) {
    uint32_t a;
    asm("{ .reg .u64 t; cvta.to.shared.u64 t, %1; cvt.u32.u64 %0, t; }" : "=r"(a) : "l"(p));
    return a;
}
__device__ __forceinline__ void ldsm4(uint32_t r[4], uint32_t addr) {
    asm volatile("ldmatrix.sync.aligned.m8n8.x4.shared.b16 {%0,%1,%2,%3}, [%4];"
                 : "=r"(r[0]), "=r"(r[1]), "=r"(r[2]), "=r"(r[3]) : "r"(addr));
}
__device__ __forceinline__ void mma16816(float d[4], const uint32_t a[4],
                                         uint32_t b0, uint32_t b1) {
    asm volatile(
        "mma.sync.aligned.m16n8k16.row.col.f32.bf16.bf16.f32 "
        "{%0,%1,%2,%3}, {%4,%5,%6,%7}, {%8,%9}, {%0,%1,%2,%3};"
        : "+f"(d[0]), "+f"(d[1]), "+f"(d[2]), "+f"(d[3])
        : "r"(a[0]), "r"(a[1]), "r"(a[2]), "r"(a[3]), "r"(b0), "r"(b1));
}
#define CP_A16(dst, src) \
    asm volatile("cp.async.cg.shared.global [%0], [%1], 16;" :: "r"(dst), "l"(src))
#define CP_A16Z(dst, src, n) \
    asm volatile("cp.async.cg.shared.global [%0], [%1], 16, %2;" :: "r"(dst), "l"(src), "r"(n))
#define CP_COMMIT()      asm volatile("cp.async.commit_group;" ::: "memory")
#define CP_WAIT_GROUP(n) asm volatile("cp.async.wait_group %0;" :: "n"(n) : "memory")

__device__ __forceinline__ uint32_t pack2(__nv_bfloat16 a, __nv_bfloat16 b) {
    __nv_bfloat162 t; t.x = a; t.y = b;
    return *(uint32_t*)&t;
}

// 64B-row swizzle: 16B chunk index XORed with (row>>1)&3.
// Conflict-free for both the STS.128 fill and ldmatrix reads.
__device__ __forceinline__ uint32_t sw_off(int row, int chunk) {
    return (uint32_t)(row * 64 + ((chunk ^ ((row >> 1) & 3)) << 4));
}

// ---------------------------------------------------------------------------
// Kernel 1: crop_and_resize + 2x2 maxpool, emits bf16 hi/lo split directly.
// ---------------------------------------------------------------------------
__global__ __launch_bounds__(128)
void roi_pool_kernel(const float* __restrict__ feats,
                     const float* __restrict__ props,
                     __nv_bfloat16* __restrict__ x0h,
                     __nv_bfloat16* __restrict__ x0l)
{
    const int n  = blockIdx.x;
    const int py = blockIdx.y;
    const int c4 = threadIdx.x;

    const float y1 = props[n*4 + 0];
    const float x1 = props[n*4 + 1];
    const float y2 = props[n*4 + 2];
    const float x2 = props[n*4 + 3];

    const float Hm1 = (float)(FH - 1);
    const float Wm1 = (float)(FW - 1);
    const float ystep = (y2 - y1) * Hm1 * (1.0f / (CROP - 1));
    const float xstep = (x2 - x1) * Wm1 * (1.0f / (CROP - 1));
    const float ybase = y1 * Hm1;
    const float xbase = x1 * Wm1;

    int   y0i[2], y1i[2];
    float wy[2];
    #pragma unroll
    for (int dy = 0; dy < 2; dy++) {
        float ys = ybase + (float)(2*py + dy) * ystep;
        float yf = floorf(ys);
        wy[dy] = ys - yf;
        int yi = (int)yf;
        if (yi < 0) yi = 0;
        if (yi > FH-1) yi = FH-1;
        y0i[dy] = yi;
        y1i[dy] = (yi + 1 < FH-1) ? (yi + 1) : (FH-1);
    }

    for (int px = 0; px < POOL; px++) {
        float4 mx = make_float4(-1e30f, -1e30f, -1e30f, -1e30f);
        #pragma unroll
        for (int dx = 0; dx < 2; dx++) {
            float xs = xbase + (float)(2*px + dx) * xstep;
            float xf = floorf(xs);
            float wx = xs - xf;
            int xi = (int)xf;
            if (xi < 0) xi = 0;
            if (xi > FW-1) xi = FW-1;
            int x0c = xi;
            int x1c = (xi + 1 < FW-1) ? (xi + 1) : (FW-1);
            #pragma unroll
            for (int dy = 0; dy < 2; dy++) {
                const float4* r0 = (const float4*)&feats[((size_t)y0i[dy]*FW)*FCH];
                const float4* r1 = (const float4*)&feats[((size_t)y1i[dy]*FW)*FCH];
                float4 v00 = r0[(size_t)x0c*(FCH/4) + c4];
                float4 v01 = r0[(size_t)x1c*(FCH/4) + c4];
                float4 v10 = r1[(size_t)x0c*(FCH/4) + c4];
                float4 v11 = r1[(size_t)x1c*(FCH/4) + c4];
                float w = wy[dy];
                float4 top, bot, val;
                top.x = v00.x + (v01.x - v00.x) * wx;
                top.y = v00.y + (v01.y - v00.y) * wx;
                top.z = v00.z + (v01.z - v00.z) * wx;
                top.w = v00.w + (v01.w - v00.w) * wx;
                bot.x = v10.x + (v11.x - v10.x) * wx;
                bot.y = v10.y + (v11.y - v10.y) * wx;
                bot.z = v10.z + (v11.z - v10.z) * wx;
                bot.w = v10.w + (v11.w - v10.w) * wx;
                val.x = top.x + (bot.x - top.x) * w;
                val.y = top.y + (bot.y - top.y) * w;
                val.z = top.z + (bot.z - top.z) * w;
                val.w = top.w + (bot.w - top.w) * w;
                mx.x = fmaxf(mx.x, val.x);
                mx.y = fmaxf(mx.y, val.y);
                mx.z = fmaxf(mx.z, val.z);
                mx.w = fmaxf(mx.w, val.w);
            }
        }
        const float* v = (const float*)&mx;
        __nv_bfloat16 h[4], l[4];
        #pragma unroll
        for (int e = 0; e < 4; e++) {
            h[e] = __float2bfloat16_rn(v[e]);
            l[e] = __float2bfloat16_rn(v[e] - __bfloat162float(h[e]));
        }
        size_t idx = (size_t)n*DFLAT + ((size_t)(py*POOL + px))*FCH + (size_t)c4*4;
        *(uint2*)&x0h[idx] = make_uint2(pack2(h[0],h[1]), pack2(h[2],h[3]));
        *(uint2*)&x0l[idx] = make_uint2(pack2(l[0],l[1]), pack2(l[2],l[3]));
    }
}

// ---------------------------------------------------------------------------
// Kernel 2: W [K,N] fp32 -> W^T hi/lo [N,K] bf16.
// ---------------------------------------------------------------------------
__global__ __launch_bounds__(256)
void convert_w_kernel(const float* __restrict__ W,
                      __nv_bfloat16* __restrict__ Th,
                      __nv_bfloat16* __restrict__ Tl,
                      int K, int N)
{
    __shared__ float ts[64][33];
    const int tx = threadIdx.x & 31;
    const int ty = threadIdx.x >> 5;
    const int kb = blockIdx.y * 64;
    const int nb = blockIdx.x * 32;

    #pragma unroll
    for (int j = 0; j < 8; j++) {
        int r = ty + j * 8;
        ts[r][tx] = W[(size_t)(kb + r) * N + nb + tx];
    }
    __syncthreads();

    #pragma unroll
    for (int j = 0; j < 4; j++) {
        int n = ty + j * 8;
        float a = ts[2*tx][n];
        float b = ts[2*tx + 1][n];
        __nv_bfloat16 ah = __float2bfloat16_rn(a);
        __nv_bfloat16 bh = __float2bfloat16_rn(b);
        __nv_bfloat16 al = __float2bfloat16_rn(a - __bfloat162float(ah));
        __nv_bfloat16 bl = __float2bfloat16_rn(b - __bfloat162float(bh));
        size_t o = (size_t)(nb + n) * K + kb + 2 * tx;
        *(uint32_t*)&Th[o] = pack2(ah, bh);
        *(uint32_t*)&Tl[o] = pack2(al, bl);
    }
}

// ---------------------------------------------------------------------------
// Kernel 3: HMMA bf16 3-product GEMM.
// BM=128, BN=128, BK=32, 256 threads, warp tile 64x32, 3-stage cp.async,
// 64B swizzled smem rows, 2 CTAs/SM.
// ---------------------------------------------------------------------------
#define A_H 0
#define A_L 8192
#define B_H 16384
#define B_L 24576
#define STAGE  32768
#define NSTAGE 3
#define GEMM_SMEM (NSTAGE * STAGE)     // 98304 B -> 2 CTAs/SM

__global__ __launch_bounds__(256, 2)
void gemm_tc_kernel(const __nv_bfloat16* __restrict__ Ah,
                    const __nv_bfloat16* __restrict__ Al,
                    int m_real,
                    const __nv_bfloat16* __restrict__ Bh,
                    const __nv_bfloat16* __restrict__ Bl,
                    const float* __restrict__ bias,
                    float* __restrict__ Cf,
                    __nv_bfloat16* __restrict__ Ch,
                    __nv_bfloat16* __restrict__ Cl,
                    int K, int out_bf16)
{
    extern __shared__ char smem[];
    const uint32_t sb0 = smem_u32(smem);
    const int tid  = threadIdx.x;
    const int wid  = tid >> 5;
    const int lane = tid & 31;
    const int wm   = wid & 1;            // 0..1 (M groups of 64)
    const int wn   = wid >> 1;           // 0..3 (N groups of 32)
    const int bn = blockIdx.x, bm = blockIdx.y;
    const int nch = K >> 5;

    // ---- load roles: 2 rows per thread per matrix ----
    const int lr = tid >> 2;             // 0..63
    const int lc = tid & 3;              // 16B chunk within 64B row
    int  a_gm[2];  uint32_t a_fill[2];  const __nv_bfloat16 *ahs[2], *als[2];
    const __nv_bfloat16 *bhs[2], *bls[2];
    uint32_t dofs[2];
    #pragma unroll
    for (int p = 0; p < 2; p++) {
        int row = lr + p * 64;
        a_gm[p]  = bm * 128 + row;
        a_fill[p] = (a_gm[p] < m_real) ? 16u : 0u;
        int sr = (a_gm[p] < m_real) ? a_gm[p] : (m_real - 1);
        ahs[p] = Ah + (size_t)sr * K + lc * 8;
        als[p] = Al + (size_t)sr * K + lc * 8;
        bhs[p] = Bh + (size_t)(bn * 128 + row) * K + lc * 8;
        bls[p] = Bl + (size_t)(bn * 128 + row) * K + lc * 8;
        dofs[p] = sw_off(row, lc);
    }

    float acc[4][4][4];
    #pragma unroll
    for (int i = 0; i < 4; i++)
        #pragma unroll
        for (int j = 0; j < 4; j++)
            #pragma unroll
            for (int e = 0; e < 4; e++) acc[i][j][e] = 0.0f;

    // ---- prologue: stages 0,1 ----
    #pragma unroll
    for (int s = 0; s < 2; s++) {
        const uint32_t st = sb0 + (uint32_t)s * STAGE;
        const int k0 = s * 32;
        #pragma unroll
        for (int p = 0; p < 2; p++) {
            CP_A16Z(st + A_H + dofs[p], ahs[p] + k0, a_fill[p]);
            CP_A16Z(st + A_L + dofs[p], als[p] + k0, a_fill[p]);
            CP_A16(st + B_H + dofs[p], bhs[p] + k0);
            CP_A16(st + B_L + dofs[p], bls[p] + k0);
        }
        CP_COMMIT();
    }

    for (int c = 0; c < nch; c++) {
        const uint32_t st = sb0 + (uint32_t)(c % NSTAGE) * STAGE;
        CP_WAIT_GROUP(1);
        __syncthreads();

        if (c + 2 < nch) {
            const uint32_t sn = sb0 + (uint32_t)((c + 2) % NSTAGE) * STAGE;
            const int k0 = (c + 2) * 32;
            #pragma unroll
            for (int p = 0; p < 2; p++) {
                CP_A16Z(sn + A_H + dofs[p], ahs[p] + k0, a_fill[p]);
                CP_A16Z(sn + A_L + dofs[p], als[p] + k0, a_fill[p]);
                CP_A16(sn + B_H + dofs[p], bhs[p] + k0);
                CP_A16(sn + B_L + dofs[p], bls[p] + k0);
            }
            CP_COMMIT();
        }

        #pragma unroll
        for (int kk = 0; kk < 2; kk++) {
            const int chunk = kk * 2 + (lane >> 4);   // 16B chunk for this lane
            const int lrow  = lane & 15;
            // B rows for this warp
            uint32_t qh[2][4], ql[2][4];
            #pragma unroll
            for (int nt2 = 0; nt2 < 2; nt2++) {
                int r = wn*32 + nt2*16 + lrow;
                uint32_t rb = st + sw_off(r, chunk);
                ldsm4(qh[nt2], rb + B_H);
                ldsm4(ql[nt2], rb + B_L);
            }
            // A-hi rows
            uint32_t ah4[4][4];
            #pragma unroll
            for (int mt = 0; mt < 4; mt++) {
                int r = wm*64 + mt*16 + lrow;
                ldsm4(ah4[mt], st + A_H + sw_off(r, chunk));
            }
            // sweep 1: hi*hi
            #pragma unroll
            for (int mt = 0; mt < 4; mt++)
                #pragma unroll
                for (int nt2 = 0; nt2 < 2; nt2++) {
                    mma16816(acc[mt][2*nt2],   ah4[mt], qh[nt2][0], qh[nt2][2]);
                    mma16816(acc[mt][2*nt2+1], ah4[mt], qh[nt2][1], qh[nt2][3]);
                }
            // sweep 2: hi*lo
            #pragma unroll
            for (int mt = 0; mt < 4; mt++)
                #pragma unroll
                for (int nt2 = 0; nt2 < 2; nt2++) {
                    mma16816(acc[mt][2*nt2],   ah4[mt], ql[nt2][0], ql[nt2][2]);
                    mma16816(acc[mt][2*nt2+1], ah4[mt], ql[nt2][1], ql[nt2][3]);
                }
            // A-lo rows, sweep 3: lo*hi
            uint32_t al4[4][4];
            #pragma unroll
            for (int mt = 0; mt < 4; mt++) {
                int r = wm*64 + mt*16 + lrow;
                ldsm4(al4[mt], st + A_L + sw_off(r, chunk));
            }
            #pragma unroll
            for (int mt = 0; mt < 4; mt++)
                #pragma unroll
                for (int nt2 = 0; nt2 < 2; nt2++) {
                    mma16816(acc[mt][2*nt2],   al4[mt], qh[nt2][0], qh[nt2][2]);
                    mma16816(acc[mt][2*nt2+1], al4[mt], qh[nt2][1], qh[nt2][3]);
                }
        }
    }

    // ---- epilogue: bias + relu ----
    #pragma unroll
    for (int mt = 0; mt < 4; mt++) {
        const int row0 = bm*128 + wm*64 + mt*16 + (lane >> 2);
        #pragma unroll
        for (int nt = 0; nt < 4; nt++) {
            const int gn = bn*128 + wn*32 + nt*8 + 2*(lane & 3);
            const float b0 = bias[gn], b1 = bias[gn+1];
            float v00 = fmaxf(acc[mt][nt][0] + b0, 0.f);
            float v01 = fmaxf(acc[mt][nt][1] + b1, 0.f);
            float v10 = fmaxf(acc[mt][nt][2] + b0, 0.f);
            float v11 = fmaxf(acc[mt][nt][3] + b1, 0.f);
            if (out_bf16) {
                __nv_bfloat16 h00 = __float2bfloat16_rn(v00);
                __nv_bfloat16 h01 = __float2bfloat16_rn(v01);
                __nv_bfloat16 h10 = __float2bfloat16_rn(v10);
                __nv_bfloat16 h11 = __float2bfloat16_rn(v11);
                __nv_bfloat16 l00 = __float2bfloat16_rn(v00 - __bfloat162float(h00));
                __nv_bfloat16 l01 = __float2bfloat16_rn(v01 - __bfloat162float(h01));
                __nv_bfloat16 l10 = __float2bfloat16_rn(v10 - __bfloat162float(h10));
                __nv_bfloat16 l11 = __float2bfloat16_rn(v11 - __bfloat162float(h11));
                *(uint32_t*)&Ch[(size_t)row0 * DHID + gn]     = pack2(h00, h01);
                *(uint32_t*)&Cl[(size_t)row0 * DHID + gn]     = pack2(l00, l01);
                *(uint32_t*)&Ch[(size_t)(row0+8) * DHID + gn] = pack2(h10, h11);
                *(uint32_t*)&Cl[(size_t)(row0+8) * DHID + gn] = pack2(l10, l11);
            } else {
                *(float2*)&Cf[(size_t)row0 * DHID + gn]     = make_float2(v00, v01);
                *(float2*)&Cf[(size_t)(row0+8) * DHID + gn] = make_float2(v10, v11);
            }
        }
    }
}

// ---------------------------------------------------------------------------
// Kernel 4: heads, 8 ROIs per block.
// ---------------------------------------------------------------------------
#define HEAD_SMEM (8 * DHID * 4 + 8 * 32 * 4)

__global__ __launch_bounds__(128)
void head_kernel(const float* __restrict__ X,
                 const float* __restrict__ Wc, const float* __restrict__ bc,
                 const float* __restrict__ Wr, const float* __restrict__ br,
                 float* __restrict__ out)
{
    extern __shared__ float xs[];             // [4096][8]
    float* logits = xs + 8 * DHID;            // [8][32]
    const int b = blockIdx.x, t = threadIdx.x;

    for (int idx = t; idx < 8 * DHID; idx += 128) {
        int r = idx >> 12, k = idx & (DHID - 1);
        xs[k * 8 + r] = X[(size_t)(b * 8 + r) * DHID + k];
    }
    __syncthreads();

    if (t < NCLS + NREG) {
        const bool is_cls = (t < NCLS);
        const float* W = is_cls ? Wc : Wr;
        const int nc   = is_cls ? NCLS : NREG;
        const int j    = is_cls ? t : (t - NCLS);
        const float bv = is_cls ? bc[j] : br[j];
        float acc[8];
        #pragma unroll
        for (int r = 0; r < 8; r++) acc[r] = bv;
        #pragma unroll 4
        for (int k = 0; k < DHID; k++) {
            float w = W[(size_t)k * nc + j];
            float4 a = *(float4*)&xs[k * 8];
            float4 bq = *(float4*)&xs[k * 8 + 4];
            acc[0] = fmaf(a.x,  w, acc[0]);
            acc[1] = fmaf(a.y,  w, acc[1]);
            acc[2] = fmaf(a.z,  w, acc[2]);
            acc[3] = fmaf(a.w,  w, acc[3]);
            acc[4] = fmaf(bq.x, w, acc[4]);
            acc[5] = fmaf(bq.y, w, acc[5]);
            acc[6] = fmaf(bq.z, w, acc[6]);
            acc[7] = fmaf(bq.w, w, acc[7]);
        }
        if (is_cls) {
            #pragma unroll
            for (int r = 0; r < 8; r++) logits[r * 32 + j] = acc[r];
        } else {
            #pragma unroll
            for (int r = 0; r < 8; r++)
                out[(size_t)N_ROI * NCLS + (size_t)(b * 8 + r) * NREG + j] = acc[r];
        }
    }
    __syncthreads();

    if (t < 8) {
        int roi = b * 8 + t;
        float m = logits[t * 32];
        #pragma unroll
        for (int j = 1; j < NCLS; j++) m = fmaxf(m, logits[t * 32 + j]);
        float e[NCLS], s = 0.f;
        #pragma unroll
        for (int j = 0; j < NCLS; j++) { e[j] = expf(logits[t * 32 + j] - m); s += e[j]; }
        float inv = 1.0f / s;
        #pragma unroll
        for (int j = 0; j < NCLS; j++) out[(size_t)roi * NCLS + j] = e[j] * inv;
    }
}

// ---------------------------------------------------------------------------
// Launch
// ---------------------------------------------------------------------------
extern "C" void kernel_launch(void* const* d_in, const int* in_sizes, int n_in,
                              void* d_out, int out_size)
{
    const float* feats = (const float*)d_in[0];
    const float* props = (const float*)d_in[1];
    const float* W1    = (const float*)d_in[2];
    const float* b1    = (const float*)d_in[3];
    const float* W2    = (const float*)d_in[4];
    const float* b2    = (const float*)d_in[5];
    const float* Wc    = (const float*)d_in[6];
    const float* bc    = (const float*)d_in[7];
    const float* Wr    = (const float*)d_in[8];
    const float* br    = (const float*)d_in[9];
    float* out = (float*)d_out;

    __nv_bfloat16 *x0h, *x0l, *x1h, *x1l, *w1h, *w1l, *w2h, *w2l;
    float *x2;
    cudaGetSymbolAddress((void**)&x0h, g_x0h);
    cudaGetSymbolAddress((void**)&x0l, g_x0l);
    cudaGetSymbolAddress((void**)&x1h, g_x1h);
    cudaGetSymbolAddress((void**)&x1l, g_x1l);
    cudaGetSymbolAddress((void**)&x2,  g_x2);
    cudaGetSymbolAddress((void**)&w1h, g_w1h);
    cudaGetSymbolAddress((void**)&w1l, g_w1l);
    cudaGetSymbolAddress((void**)&w2h, g_w2h);
    cudaGetSymbolAddress((void**)&w2l, g_w2l);

    cudaFuncSetAttribute(gemm_tc_kernel, cudaFuncAttributeMaxDynamicSharedMemorySize, GEMM_SMEM);
    cudaFuncSetAttribute(head_kernel,    cudaFuncAttributeMaxDynamicSharedMemorySize, HEAD_SMEM);

    // 1. ROI crop_and_resize + maxpool -> x0 bf16 hi/lo
    roi_pool_kernel<<<dim3(N_ROI, POOL), 128>>>(feats, props, x0h, x0l);

    // 2. Weight convert+transpose -> bf16 hi/lo K-major
    convert_w_kernel<<<dim3(DHID / 32, DFLAT / 64), 256>>>(W1, w1h, w1l, DFLAT, DHID);
    convert_w_kernel<<<dim3(DHID / 32, DHID  / 64), 256>>>(W2, w2h, w2l, DHID,  DHID);

    // 3. FC1 -> x1 bf16 hi/lo
    gemm_tc_kernel<<<dim3(DHID / 128, M_PAD / 128), 256, GEMM_SMEM>>>(
        x0h, x0l, N_ROI, w1h, w1l, b1, nullptr, x1h, x1l, DFLAT, 1);

    // 4. FC2 -> x2 fp32
    gemm_tc_kernel<<<dim3(DHID / 128, M_PAD / 128), 256, GEMM_SMEM>>>(
        x1h, x1l, M_PAD, w2h, w2l, b2, x2, nullptr, nullptr, DHID, 0);

    // 5. Heads
    head_kernel<<<N_ROI / 8, 128, HEAD_SMEM>>>(x2, Wc, bc, Wr, br, out);
}

// round 10
// speedup vs baseline: 1.5501x; 1.3254x over previous
#include <cuda_runtime.h>
#include <cuda_bf16.h>
#include <cuda_fp16.h>
#include <math.h>
#include <stdint.h>

// ---------------------------------------------------------------------------
// Problem constants
// ---------------------------------------------------------------------------
#define N_ROI   1000
#define M_PAD   1024
#define FH      38
#define FW      50
#define FCH     512
#define CROP    14
#define POOL    7
#define DFLAT   25088
#define DHID    4096
#define NCLS    21
#define NREG    80

#define WSCALE     1024.0f          // weight pre-scale (2^10)
#define INV_WSCALE (1.0f/1024.0f)

// ---------------------------------------------------------------------------
// Scratch (device globals — no allocation allowed)
// ---------------------------------------------------------------------------
__device__ __half g_x0 [(size_t)M_PAD * DFLAT];      // pooled feats, fp16
__device__ __half g_x1 [(size_t)M_PAD * DHID];       // FC1 out, fp16
__device__ float  g_x2 [(size_t)M_PAD * DHID];       // FC2 out, fp32
__device__ __half g_w1h[(size_t)DHID * DFLAT];       // W1^T * 1024 hi
__device__ __half g_w1l[(size_t)DHID * DFLAT];       // W1^T * 1024 lo
__device__ __half g_w2h[(size_t)DHID * DHID];
__device__ __half g_w2l[(size_t)DHID * DHID];

// ---------------------------------------------------------------------------
// asm helpers (compute_103-safe)
// ---------------------------------------------------------------------------
__device__ __forceinline__ uint32_t smem_u32(const void* p) {
    uint32_t a;
    asm("{ .reg .u64 t; cvta.to.shared.u64 t, %1; cvt.u32.u64 %0, t; }" : "=r"(a) : "l"(p));
    return a;
}
__device__ __forceinline__ void ldsm4(uint32_t r[4], uint32_t addr) {
    asm volatile("ldmatrix.sync.aligned.m8n8.x4.shared.b16 {%0,%1,%2,%3}, [%4];"
                 : "=r"(r[0]), "=r"(r[1]), "=r"(r[2]), "=r"(r[3]) : "r"(addr));
}
__device__ __forceinline__ void mma16816(float d[4], const uint32_t a[4],
                                         uint32_t b0, uint32_t b1) {
    asm volatile(
        "mma.sync.aligned.m16n8k16.row.col.f32.f16.f16.f32 "
        "{%0,%1,%2,%3}, {%4,%5,%6,%7}, {%8,%9}, {%0,%1,%2,%3};"
        : "+f"(d[0]), "+f"(d[1]), "+f"(d[2]), "+f"(d[3])
        : "r"(a[0]), "r"(a[1]), "r"(a[2]), "r"(a[3]), "r"(b0), "r"(b1));
}
#define CP_A16(dst, src) \
    asm volatile("cp.async.cg.shared.global [%0], [%1], 16;" :: "r"(dst), "l"(src))
#define CP_A16Z(dst, src, n) \
    asm volatile("cp.async.cg.shared.global [%0], [%1], 16, %2;" :: "r"(dst), "l"(src), "r"(n))
#define CP_COMMIT()      asm volatile("cp.async.commit_group;" ::: "memory")
#define CP_WAIT_GROUP(n) asm volatile("cp.async.wait_group %0;" :: "n"(n) : "memory")

__device__ __forceinline__ uint32_t pack2h(__half a, __half b) {
    __half2 t; t.x = a; t.y = b;
    return *(uint32_t*)&t;
}

// 64B-row swizzle: 16B chunk index XORed with (row>>1)&3. Conflict-free.
__device__ __forceinline__ uint32_t sw_off(int row, int chunk) {
    return (uint32_t)(row * 64 + ((chunk ^ ((row >> 1) & 3)) << 4));
}

// ---------------------------------------------------------------------------
// Kernel 1: crop_and_resize + 2x2 maxpool, emits fp16 directly.
// ---------------------------------------------------------------------------
__global__ __launch_bounds__(128)
void roi_pool_kernel(const float* __restrict__ feats,
                     const float* __restrict__ props,
                     __half* __restrict__ x0)
{
    const int n  = blockIdx.x;
    const int py = blockIdx.y;
    const int c4 = threadIdx.x;

    const float y1 = props[n*4 + 0];
    const float x1 = props[n*4 + 1];
    const float y2 = props[n*4 + 2];
    const float x2 = props[n*4 + 3];

    const float Hm1 = (float)(FH - 1);
    const float Wm1 = (float)(FW - 1);
    const float ystep = (y2 - y1) * Hm1 * (1.0f / (CROP - 1));
    const float xstep = (x2 - x1) * Wm1 * (1.0f / (CROP - 1));
    const float ybase = y1 * Hm1;
    const float xbase = x1 * Wm1;

    int   y0i[2], y1i[2];
    float wy[2];
    #pragma unroll
    for (int dy = 0; dy < 2; dy++) {
        float ys = ybase + (float)(2*py + dy) * ystep;
        float yf = floorf(ys);
        wy[dy] = ys - yf;
        int yi = (int)yf;
        if (yi < 0) yi = 0;
        if (yi > FH-1) yi = FH-1;
        y0i[dy] = yi;
        y1i[dy] = (yi + 1 < FH-1) ? (yi + 1) : (FH-1);
    }

    for (int px = 0; px < POOL; px++) {
        float4 mx = make_float4(-1e30f, -1e30f, -1e30f, -1e30f);
        #pragma unroll
        for (int dx = 0; dx < 2; dx++) {
            float xs = xbase + (float)(2*px + dx) * xstep;
            float xf = floorf(xs);
            float wx = xs - xf;
            int xi = (int)xf;
            if (xi < 0) xi = 0;
            if (xi > FW-1) xi = FW-1;
            int x0c = xi;
            int x1c = (xi + 1 < FW-1) ? (xi + 1) : (FW-1);
            #pragma unroll
            for (int dy = 0; dy < 2; dy++) {
                const float4* r0 = (const float4*)&feats[((size_t)y0i[dy]*FW)*FCH];
                const float4* r1 = (const float4*)&feats[((size_t)y1i[dy]*FW)*FCH];
                float4 v00 = r0[(size_t)x0c*(FCH/4) + c4];
                float4 v01 = r0[(size_t)x1c*(FCH/4) + c4];
                float4 v10 = r1[(size_t)x0c*(FCH/4) + c4];
                float4 v11 = r1[(size_t)x1c*(FCH/4) + c4];
                float w = wy[dy];
                float4 top, bot, val;
                top.x = v00.x + (v01.x - v00.x) * wx;
                top.y = v00.y + (v01.y - v00.y) * wx;
                top.z = v00.z + (v01.z - v00.z) * wx;
                top.w = v00.w + (v01.w - v00.w) * wx;
                bot.x = v10.x + (v11.x - v10.x) * wx;
                bot.y = v10.y + (v11.y - v10.y) * wx;
                bot.z = v10.z + (v11.z - v10.z) * wx;
                bot.w = v10.w + (v11.w - v10.w) * wx;
                val.x = top.x + (bot.x - top.x) * w;
                val.y = top.y + (bot.y - top.y) * w;
                val.z = top.z + (bot.z - top.z) * w;
                val.w = top.w + (bot.w - top.w) * w;
                mx.x = fmaxf(mx.x, val.x);
                mx.y = fmaxf(mx.y, val.y);
                mx.z = fmaxf(mx.z, val.z);
                mx.w = fmaxf(mx.w, val.w);
            }
        }
        size_t idx = (size_t)n*DFLAT + ((size_t)(py*POOL + px))*FCH + (size_t)c4*4;
        *(uint2*)&x0[idx] = make_uint2(
            pack2h(__float2half_rn(mx.x), __float2half_rn(mx.y)),
            pack2h(__float2half_rn(mx.z), __float2half_rn(mx.w)));
    }
}

// ---------------------------------------------------------------------------
// Kernel 2: W [K,N] fp32 -> W^T*1024 hi/lo [N,K] fp16.
// ---------------------------------------------------------------------------
__global__ __launch_bounds__(256)
void convert_w_kernel(const float* __restrict__ W,
                      __half* __restrict__ Th,
                      __half* __restrict__ Tl,
                      int K, int N)
{
    __shared__ float ts[64][33];
    const int tx = threadIdx.x & 31;
    const int ty = threadIdx.x >> 5;
    const int kb = blockIdx.y * 64;
    const int nb = blockIdx.x * 32;

    #pragma unroll
    for (int j = 0; j < 8; j++) {
        int r = ty + j * 8;
        ts[r][tx] = W[(size_t)(kb + r) * N + nb + tx];
    }
    __syncthreads();

    #pragma unroll
    for (int j = 0; j < 4; j++) {
        int n = ty + j * 8;
        float a = ts[2*tx][n]     * WSCALE;
        float b = ts[2*tx + 1][n] * WSCALE;
        __half ah = __float2half_rn(a);
        __half bh = __float2half_rn(b);
        __half al = __float2half_rn(a - __half2float(ah));
        __half bl = __float2half_rn(b - __half2float(bh));
        size_t o = (size_t)(nb + n) * K + kb + 2 * tx;
        *(uint32_t*)&Th[o] = pack2h(ah, bh);
        *(uint32_t*)&Tl[o] = pack2h(al, bl);
    }
}

// ---------------------------------------------------------------------------
// Kernel 3: HMMA fp16 2-product GEMM.
// D = relu((A @ (Bh+Bl)^T) * 2^-10 + bias); A fp16, B scaled hi/lo fp16.
// BM=128, BN=128, BK=32, 256 threads, warp tile 64x32, 4-stage cp.async,
// 64B swizzled rows, 2 CTAs/SM.
// ---------------------------------------------------------------------------
#define A_S 0
#define B_H 8192
#define B_L 16384
#define STAGE  24576
#define NSTAGE 4
#define GEMM_SMEM (NSTAGE * STAGE)     // 98304 B -> 2 CTAs/SM

__global__ __launch_bounds__(256, 2)
void gemm_tc_kernel(const __half* __restrict__ A,
                    int m_real,
                    const __half* __restrict__ Bh,
                    const __half* __restrict__ Bl,
                    const float* __restrict__ bias,
                    float* __restrict__ Cf,
                    __half* __restrict__ Chf,
                    int K, int out_f16)
{
    extern __shared__ char smem[];
    const uint32_t sb0 = smem_u32(smem);
    const int tid  = threadIdx.x;
    const int wid  = tid >> 5;
    const int lane = tid & 31;
    const int wm   = wid & 1;            // 0..1 (M groups of 64)
    const int wn   = wid >> 1;           // 0..3 (N groups of 32)
    const int bn = blockIdx.x, bm = blockIdx.y;
    const int nch = K >> 5;

    // ---- load roles: rows lr and lr+64, 16B chunk lc ----
    const int lr = tid >> 2;             // 0..63
    const int lc = tid & 3;
    uint32_t a_fill[2]; const __half *as[2], *bhs[2], *bls[2];
    uint32_t dofs[2];
    #pragma unroll
    for (int p = 0; p < 2; p++) {
        int row = lr + p * 64;
        int gm  = bm * 128 + row;
        a_fill[p] = (gm < m_real) ? 16u : 0u;
        int sr = (gm < m_real) ? gm : (m_real - 1);
        as[p]  = A  + (size_t)sr * K + lc * 8;
        bhs[p] = Bh + (size_t)(bn * 128 + row) * K + lc * 8;
        bls[p] = Bl + (size_t)(bn * 128 + row) * K + lc * 8;
        dofs[p] = sw_off(row, lc);
    }

    float acc[4][4][4];
    #pragma unroll
    for (int i = 0; i < 4; i++)
        #pragma unroll
        for (int j = 0; j < 4; j++)
            #pragma unroll
            for (int e = 0; e < 4; e++) acc[i][j][e] = 0.0f;

    // ---- prologue: stages 0..2 ----
    #pragma unroll
    for (int s = 0; s < 3; s++) {
        const uint32_t st = sb0 + (uint32_t)s * STAGE;
        const int k0 = s * 32;
        #pragma unroll
        for (int p = 0; p < 2; p++) {
            CP_A16Z(st + A_S + dofs[p], as[p] + k0, a_fill[p]);
            CP_A16(st + B_H + dofs[p], bhs[p] + k0);
            CP_A16(st + B_L + dofs[p], bls[p] + k0);
        }
        CP_COMMIT();
    }

    for (int c = 0; c < nch; c++) {
        const uint32_t st = sb0 + (uint32_t)(c % NSTAGE) * STAGE;
        CP_WAIT_GROUP(2);
        __syncthreads();

        if (c + 3 < nch) {
            const uint32_t sn = sb0 + (uint32_t)((c + 3) % NSTAGE) * STAGE;
            const int k0 = (c + 3) * 32;
            #pragma unroll
            for (int p = 0; p < 2; p++) {
                CP_A16Z(sn + A_S + dofs[p], as[p] + k0, a_fill[p]);
                CP_A16(sn + B_H + dofs[p], bhs[p] + k0);
                CP_A16(sn + B_L + dofs[p], bls[p] + k0);
            }
            CP_COMMIT();
        }

        #pragma unroll
        for (int kk = 0; kk < 2; kk++) {
            const int chunk = kk * 2 + (lane >> 4);
            const int lrow  = lane & 15;
            uint32_t qh[2][4], ql[2][4];
            #pragma unroll
            for (int nt2 = 0; nt2 < 2; nt2++) {
                int r = wn*32 + nt2*16 + lrow;
                uint32_t rb = st + sw_off(r, chunk);
                ldsm4(qh[nt2], rb + B_H);
                ldsm4(ql[nt2], rb + B_L);
            }
            uint32_t a4[4][4];
            #pragma unroll
            for (int mt = 0; mt < 4; mt++) {
                int r = wm*64 + mt*16 + lrow;
                ldsm4(a4[mt], st + A_S + sw_off(r, chunk));
            }
            // sweep 1: A * B_hi
            #pragma unroll
            for (int mt = 0; mt < 4; mt++)
                #pragma unroll
                for (int nt2 = 0; nt2 < 2; nt2++) {
                    mma16816(acc[mt][2*nt2],   a4[mt], qh[nt2][0], qh[nt2][2]);
                    mma16816(acc[mt][2*nt2+1], a4[mt], qh[nt2][1], qh[nt2][3]);
                }
            // sweep 2: A * B_lo
            #pragma unroll
            for (int mt = 0; mt < 4; mt++)
                #pragma unroll
                for (int nt2 = 0; nt2 < 2; nt2++) {
                    mma16816(acc[mt][2*nt2],   a4[mt], ql[nt2][0], ql[nt2][2]);
                    mma16816(acc[mt][2*nt2+1], a4[mt], ql[nt2][1], ql[nt2][3]);
                }
        }
    }

    // ---- epilogue: descale + bias + relu ----
    #pragma unroll
    for (int mt = 0; mt < 4; mt++) {
        const int row0 = bm*128 + wm*64 + mt*16 + (lane >> 2);
        #pragma unroll
        for (int nt = 0; nt < 4; nt++) {
            const int gn = bn*128 + wn*32 + nt*8 + 2*(lane & 3);
            const float b0 = bias[gn], b1 = bias[gn+1];
            float v00 = fmaxf(fmaf(acc[mt][nt][0], INV_WSCALE, b0), 0.f);
            float v01 = fmaxf(fmaf(acc[mt][nt][1], INV_WSCALE, b1), 0.f);
            float v10 = fmaxf(fmaf(acc[mt][nt][2], INV_WSCALE, b0), 0.f);
            float v11 = fmaxf(fmaf(acc[mt][nt][3], INV_WSCALE, b1), 0.f);
            if (out_f16) {
                *(uint32_t*)&Chf[(size_t)row0 * DHID + gn] =
                    pack2h(__float2half_rn(v00), __float2half_rn(v01));
                *(uint32_t*)&Chf[(size_t)(row0+8) * DHID + gn] =
                    pack2h(__float2half_rn(v10), __float2half_rn(v11));
            } else {
                *(float2*)&Cf[(size_t)row0 * DHID + gn]     = make_float2(v00, v01);
                *(float2*)&Cf[(size_t)(row0+8) * DHID + gn] = make_float2(v10, v11);
            }
        }
    }
}

// ---------------------------------------------------------------------------
// Kernel 4: heads, 8 ROIs per block.
// ---------------------------------------------------------------------------
#define HEAD_SMEM (8 * DHID * 4 + 8 * 32 * 4)

__global__ __launch_bounds__(128)
void head_kernel(const float* __restrict__ X,
                 const float* __restrict__ Wc, const float* __restrict__ bc,
                 const float* __restrict__ Wr, const float* __restrict__ br,
                 float* __restrict__ out)
{
    extern __shared__ float xs[];             // [4096][8]
    float* logits = xs + 8 * DHID;            // [8][32]
    const int b = blockIdx.x, t = threadIdx.x;

    for (int idx = t; idx < 8 * DHID; idx += 128) {
        int r = idx >> 12, k = idx & (DHID - 1);
        xs[k * 8 + r] = X[(size_t)(b * 8 + r) * DHID + k];
    }
    __syncthreads();

    if (t < NCLS + NREG) {
        const bool is_cls = (t < NCLS);
        const float* W = is_cls ? Wc : Wr;
        const int nc   = is_cls ? NCLS : NREG;
        const int j    = is_cls ? t : (t - NCLS);
        const float bv = is_cls ? bc[j] : br[j];
        float acc[8];
        #pragma unroll
        for (int r = 0; r < 8; r++) acc[r] = bv;
        #pragma unroll 4
        for (int k = 0; k < DHID; k++) {
            float w = W[(size_t)k * nc + j];
            float4 a = *(float4*)&xs[k * 8];
            float4 bq = *(float4*)&xs[k * 8 + 4];
            acc[0] = fmaf(a.x,  w, acc[0]);
            acc[1] = fmaf(a.y,  w, acc[1]);
            acc[2] = fmaf(a.z,  w, acc[2]);
            acc[3] = fmaf(a.w,  w, acc[3]);
            acc[4] = fmaf(bq.x, w, acc[4]);
            acc[5] = fmaf(bq.y, w, acc[5]);
            acc[6] = fmaf(bq.z, w, acc[6]);
            acc[7] = fmaf(bq.w, w, acc[7]);
        }
        if (is_cls) {
            #pragma unroll
            for (int r = 0; r < 8; r++) logits[r * 32 + j] = acc[r];
        } else {
            #pragma unroll
            for (int r = 0; r < 8; r++)
                out[(size_t)N_ROI * NCLS + (size_t)(b * 8 + r) * NREG + j] = acc[r];
        }
    }
    __syncthreads();

    if (t < 8) {
        int roi = b * 8 + t;
        float m = logits[t * 32];
        #pragma unroll
        for (int j = 1; j < NCLS; j++) m = fmaxf(m, logits[t * 32 + j]);
        float e[NCLS], s = 0.f;
        #pragma unroll
        for (int j = 0; j < NCLS; j++) { e[j] = expf(logits[t * 32 + j] - m); s += e[j]; }
        float inv = 1.0f / s;
        #pragma unroll
        for (int j = 0; j < NCLS; j++) out[(size_t)roi * NCLS + j] = e[j] * inv;
    }
}

// ---------------------------------------------------------------------------
// Launch
// ---------------------------------------------------------------------------
extern "C" void kernel_launch(void* const* d_in, const int* in_sizes, int n_in,
                              void* d_out, int out_size)
{
    const float* feats = (const float*)d_in[0];
    const float* props = (const float*)d_in[1];
    const float* W1    = (const float*)d_in[2];
    const float* b1    = (const float*)d_in[3];
    const float* W2    = (const float*)d_in[4];
    const float* b2    = (const float*)d_in[5];
    const float* Wc    = (const float*)d_in[6];
    const float* bc    = (const float*)d_in[7];
    const float* Wr    = (const float*)d_in[8];
    const float* br    = (const float*)d_in[9];
    float* out = (float*)d_out;

    __half *x0, *x1, *w1h, *w1l, *w2h, *w2l;
    float *x2;
    cudaGetSymbolAddress((void**)&x0,  g_x0);
    cudaGetSymbolAddress((void**)&x1,  g_x1);
    cudaGetSymbolAddress((void**)&x2,  g_x2);
    cudaGetSymbolAddress((void**)&w1h, g_w1h);
    cudaGetSymbolAddress((void**)&w1l, g_w1l);
    cudaGetSymbolAddress((void**)&w2h, g_w2h);
    cudaGetSymbolAddress((void**)&w2l, g_w2l);

    cudaFuncSetAttribute(gemm_tc_kernel, cudaFuncAttributeMaxDynamicSharedMemorySize, GEMM_SMEM);
    cudaFuncSetAttribute(head_kernel,    cudaFuncAttributeMaxDynamicSharedMemorySize, HEAD_SMEM);

    // 1. ROI crop_and_resize + maxpool -> x0 fp16
    roi_pool_kernel<<<dim3(N_ROI, POOL), 128>>>(feats, props, x0);

    // 2. Weight convert+transpose -> fp16*1024 hi/lo K-major
    convert_w_kernel<<<dim3(DHID / 32, DFLAT / 64), 256>>>(W1, w1h, w1l, DFLAT, DHID);
    convert_w_kernel<<<dim3(DHID / 32, DHID  / 64), 256>>>(W2, w2h, w2l, DHID,  DHID);

    // 3. FC1 -> x1 fp16
    gemm_tc_kernel<<<dim3(DHID / 128, M_PAD / 128), 256, GEMM_SMEM>>>(
        x0, N_ROI, w1h, w1l, b1, nullptr, x1, DFLAT, 1);

    // 4. FC2 -> x2 fp32
    gemm_tc_kernel<<<dim3(DHID / 128, M_PAD / 128), 256, GEMM_SMEM>>>(
        x1, M_PAD, w2h, w2l, b2, x2, nullptr, DHID, 0);

    // 5. Heads
    head_kernel<<<N_ROI / 8, 128, HEAD_SMEM>>>(x2, Wc, bc, Wr, br, out);
}

// round 13
// speedup vs baseline: 2.3549x; 1.5191x over previous
#include <cuda_runtime.h>
#include <cuda_bf16.h>
#include <cuda_fp16.h>
#include <math.h>
#include <stdint.h>

// ---------------------------------------------------------------------------
// Problem constants
// ---------------------------------------------------------------------------
#define N_ROI   1000
#define M_PAD   1024
#define FH      38
#define FW      50
#define FCH     512
#define CROP    14
#define POOL    7
#define DFLAT   25088
#define DHID    4096
#define NCLS    21
#define NREG    80

#define WSCALE     1024.0f          // weight pre-scale (2^10)
#define INV_WSCALE (1.0f/1024.0f)

// ---------------------------------------------------------------------------
// Scratch (device globals — no allocation allowed)
// ---------------------------------------------------------------------------
__device__ __half g_x0 [(size_t)M_PAD * DFLAT];      // pooled feats, fp16
__device__ __half g_x1 [(size_t)M_PAD * DHID];       // FC1 out, fp16
__device__ float  g_x2 [(size_t)M_PAD * DHID];       // FC2 out, fp32
__device__ __half g_w1 [(size_t)DHID * DFLAT];       // W1^T * 1024 fp16
__device__ __half g_w2 [(size_t)DHID * DHID];        // W2^T * 1024 fp16

// ---------------------------------------------------------------------------
// asm helpers (compute_103-safe)
// ---------------------------------------------------------------------------
__device__ __forceinline__ uint32_t smem_u32(const void* p) {
    uint32_t a;
    asm("{ .reg .u64 t; cvta.to.shared.u64 t, %1; cvt.u32.u64 %0, t; }" : "=r"(a) : "l"(p));
    return a;
}
__device__ __forceinline__ void ldsm4(uint32_t r[4], uint32_t addr) {
    asm volatile("ldmatrix.sync.aligned.m8n8.x4.shared.b16 {%0,%1,%2,%3}, [%4];"
                 : "=r"(r[0]), "=r"(r[1]), "=r"(r[2]), "=r"(r[3]) : "r"(addr));
}
__device__ __forceinline__ void mma16816(float d[4], const uint32_t a[4],
                                         uint32_t b0, uint32_t b1) {
    asm volatile(
        "mma.sync.aligned.m16n8k16.row.col.f32.f16.f16.f32 "
        "{%0,%1,%2,%3}, {%4,%5,%6,%7}, {%8,%9}, {%0,%1,%2,%3};"
        : "+f"(d[0]), "+f"(d[1]), "+f"(d[2]), "+f"(d[3])
        : "r"(a[0]), "r"(a[1]), "r"(a[2]), "r"(a[3]), "r"(b0), "r"(b1));
}
#define CP_A16(dst, src) \
    asm volatile("cp.async.cg.shared.global [%0], [%1], 16;" :: "r"(dst), "l"(src))
#define CP_A16Z(dst, src, n) \
    asm volatile("cp.async.cg.shared.global [%0], [%1], 16, %2;" :: "r"(dst), "l"(src), "r"(n))
#define CP_COMMIT()      asm volatile("cp.async.commit_group;" ::: "memory")
#define CP_WAIT_GROUP(n) asm volatile("cp.async.wait_group %0;" :: "n"(n) : "memory")

__device__ __forceinline__ uint32_t pack2h(__half a, __half b) {
    __half2 t; t.x = a; t.y = b;
    return *(uint32_t*)&t;
}

// 64B-row swizzle: 16B chunk index XORed with (row>>1)&3. Conflict-free.
__device__ __forceinline__ uint32_t sw_off(int row, int chunk) {
    return (uint32_t)(row * 64 + ((chunk ^ ((row >> 1) & 3)) << 4));
}

// ---------------------------------------------------------------------------
// Kernel 1: crop_and_resize + 2x2 maxpool, emits fp16 directly.
// ---------------------------------------------------------------------------
__global__ __launch_bounds__(128)
void roi_pool_kernel(const float* __restrict__ feats,
                     const float* __restrict__ props,
                     __half* __restrict__ x0)
{
    const int n  = blockIdx.x;
    const int py = blockIdx.y;
    const int c4 = threadIdx.x;

    const float y1 = props[n*4 + 0];
    const float x1 = props[n*4 + 1];
    const float y2 = props[n*4 + 2];
    const float x2 = props[n*4 + 3];

    const float Hm1 = (float)(FH - 1);
    const float Wm1 = (float)(FW - 1);
    const float ystep = (y2 - y1) * Hm1 * (1.0f / (CROP - 1));
    const float xstep = (x2 - x1) * Wm1 * (1.0f / (CROP - 1));
    const float ybase = y1 * Hm1;
    const float xbase = x1 * Wm1;

    int   y0i[2], y1i[2];
    float wy[2];
    #pragma unroll
    for (int dy = 0; dy < 2; dy++) {
        float ys = ybase + (float)(2*py + dy) * ystep;
        float yf = floorf(ys);
        wy[dy] = ys - yf;
        int yi = (int)yf;
        if (yi < 0) yi = 0;
        if (yi > FH-1) yi = FH-1;
        y0i[dy] = yi;
        y1i[dy] = (yi + 1 < FH-1) ? (yi + 1) : (FH-1);
    }

    for (int px = 0; px < POOL; px++) {
        float4 mx = make_float4(-1e30f, -1e30f, -1e30f, -1e30f);
        #pragma unroll
        for (int dx = 0; dx < 2; dx++) {
            float xs = xbase + (float)(2*px + dx) * xstep;
            float xf = floorf(xs);
            float wx = xs - xf;
            int xi = (int)xf;
            if (xi < 0) xi = 0;
            if (xi > FW-1) xi = FW-1;
            int x0c = xi;
            int x1c = (xi + 1 < FW-1) ? (xi + 1) : (FW-1);
            #pragma unroll
            for (int dy = 0; dy < 2; dy++) {
                const float4* r0 = (const float4*)&feats[((size_t)y0i[dy]*FW)*FCH];
                const float4* r1 = (const float4*)&feats[((size_t)y1i[dy]*FW)*FCH];
                float4 v00 = r0[(size_t)x0c*(FCH/4) + c4];
                float4 v01 = r0[(size_t)x1c*(FCH/4) + c4];
                float4 v10 = r1[(size_t)x0c*(FCH/4) + c4];
                float4 v11 = r1[(size_t)x1c*(FCH/4) + c4];
                float w = wy[dy];
                float4 top, bot, val;
                top.x = v00.x + (v01.x - v00.x) * wx;
                top.y = v00.y + (v01.y - v00.y) * wx;
                top.z = v00.z + (v01.z - v00.z) * wx;
                top.w = v00.w + (v01.w - v00.w) * wx;
                bot.x = v10.x + (v11.x - v10.x) * wx;
                bot.y = v10.y + (v11.y - v10.y) * wx;
                bot.z = v10.z + (v11.z - v10.z) * wx;
                bot.w = v10.w + (v11.w - v10.w) * wx;
                val.x = top.x + (bot.x - top.x) * w;
                val.y = top.y + (bot.y - top.y) * w;
                val.z = top.z + (bot.z - top.z) * w;
                val.w = top.w + (bot.w - top.w) * w;
                mx.x = fmaxf(mx.x, val.x);
                mx.y = fmaxf(mx.y, val.y);
                mx.z = fmaxf(mx.z, val.z);
                mx.w = fmaxf(mx.w, val.w);
            }
        }
        size_t idx = (size_t)n*DFLAT + ((size_t)(py*POOL + px))*FCH + (size_t)c4*4;
        *(uint2*)&x0[idx] = make_uint2(
            pack2h(__float2half_rn(mx.x), __float2half_rn(mx.y)),
            pack2h(__float2half_rn(mx.z), __float2half_rn(mx.w)));
    }
}

// ---------------------------------------------------------------------------
// Kernel 2: W [K,N] fp32 -> W^T*1024 [N,K] fp16 (single plane).
// ---------------------------------------------------------------------------
__global__ __launch_bounds__(256)
void convert_w_kernel(const float* __restrict__ W,
                      __half* __restrict__ T,
                      int K, int N)
{
    __shared__ float ts[64][33];
    const int tx = threadIdx.x & 31;
    const int ty = threadIdx.x >> 5;
    const int kb = blockIdx.y * 64;
    const int nb = blockIdx.x * 32;

    #pragma unroll
    for (int j = 0; j < 8; j++) {
        int r = ty + j * 8;
        ts[r][tx] = W[(size_t)(kb + r) * N + nb + tx];
    }
    __syncthreads();

    #pragma unroll
    for (int j = 0; j < 4; j++) {
        int n = ty + j * 8;
        float a = ts[2*tx][n]     * WSCALE;
        float b = ts[2*tx + 1][n] * WSCALE;
        size_t o = (size_t)(nb + n) * K + kb + 2 * tx;
        *(uint32_t*)&T[o] = pack2h(__float2half_rn(a), __float2half_rn(b));
    }
}

// ---------------------------------------------------------------------------
// Kernel 3: HMMA fp16 single-product GEMM.
// D = relu((A @ B^T) * 2^-10 + bias); A fp16, B = W^T*1024 fp16.
// BM=128, BN=128, BK=32, 256 threads, warp tile 64x32, 4-stage cp.async,
// 64B swizzled rows, 2 CTAs/SM.
// ---------------------------------------------------------------------------
#define A_S 0
#define B_S 8192
#define STAGE  16384
#define NSTAGE 4
#define GEMM_SMEM (NSTAGE * STAGE)     // 65536 B -> 2 CTAs/SM

__global__ __launch_bounds__(256, 2)
void gemm_tc_kernel(const __half* __restrict__ A,
                    int m_real,
                    const __half* __restrict__ B,
                    const float* __restrict__ bias,
                    float* __restrict__ Cf,
                    __half* __restrict__ Chf,
                    int K, int out_f16)
{
    extern __shared__ char smem[];
    const uint32_t sb0 = smem_u32(smem);
    const int tid  = threadIdx.x;
    const int wid  = tid >> 5;
    const int lane = tid & 31;
    const int wm   = wid & 1;            // 0..1 (M groups of 64)
    const int wn   = wid >> 1;           // 0..3 (N groups of 32)
    const int bn = blockIdx.x, bm = blockIdx.y;
    const int nch = K >> 5;

    // ---- load roles: rows lr and lr+64, 16B chunk lc ----
    const int lr = tid >> 2;             // 0..63
    const int lc = tid & 3;
    uint32_t a_fill[2]; const __half *as[2], *bs[2];
    uint32_t dofs[2];
    #pragma unroll
    for (int p = 0; p < 2; p++) {
        int row = lr + p * 64;
        int gm  = bm * 128 + row;
        a_fill[p] = (gm < m_real) ? 16u : 0u;
        int sr = (gm < m_real) ? gm : (m_real - 1);
        as[p] = A + (size_t)sr * K + lc * 8;
        bs[p] = B + (size_t)(bn * 128 + row) * K + lc * 8;
        dofs[p] = sw_off(row, lc);
    }

    float acc[4][4][4];
    #pragma unroll
    for (int i = 0; i < 4; i++)
        #pragma unroll
        for (int j = 0; j < 4; j++)
            #pragma unroll
            for (int e = 0; e < 4; e++) acc[i][j][e] = 0.0f;

    // ---- prologue: stages 0..2 ----
    #pragma unroll
    for (int s = 0; s < 3; s++) {
        const uint32_t st = sb0 + (uint32_t)s * STAGE;
        const int k0 = s * 32;
        #pragma unroll
        for (int p = 0; p < 2; p++) {
            CP_A16Z(st + A_S + dofs[p], as[p] + k0, a_fill[p]);
            CP_A16(st + B_S + dofs[p], bs[p] + k0);
        }
        CP_COMMIT();
    }

    for (int c = 0; c < nch; c++) {
        const uint32_t st = sb0 + (uint32_t)(c % NSTAGE) * STAGE;
        CP_WAIT_GROUP(2);
        __syncthreads();

        if (c + 3 < nch) {
            const uint32_t sn = sb0 + (uint32_t)((c + 3) % NSTAGE) * STAGE;
            const int k0 = (c + 3) * 32;
            #pragma unroll
            for (int p = 0; p < 2; p++) {
                CP_A16Z(sn + A_S + dofs[p], as[p] + k0, a_fill[p]);
                CP_A16(sn + B_S + dofs[p], bs[p] + k0);
            }
            CP_COMMIT();
        }

        #pragma unroll
        for (int kk = 0; kk < 2; kk++) {
            const int chunk = kk * 2 + (lane >> 4);
            const int lrow  = lane & 15;
            uint32_t q[2][4];
            #pragma unroll
            for (int nt2 = 0; nt2 < 2; nt2++) {
                int r = wn*32 + nt2*16 + lrow;
                ldsm4(q[nt2], st + B_S + sw_off(r, chunk));
            }
            uint32_t a4[4][4];
            #pragma unroll
            for (int mt = 0; mt < 4; mt++) {
                int r = wm*64 + mt*16 + lrow;
                ldsm4(a4[mt], st + A_S + sw_off(r, chunk));
            }
            #pragma unroll
            for (int mt = 0; mt < 4; mt++)
                #pragma unroll
                for (int nt2 = 0; nt2 < 2; nt2++) {
                    mma16816(acc[mt][2*nt2],   a4[mt], q[nt2][0], q[nt2][2]);
                    mma16816(acc[mt][2*nt2+1], a4[mt], q[nt2][1], q[nt2][3]);
                }
        }
    }

    // ---- epilogue: descale + bias + relu ----
    #pragma unroll
    for (int mt = 0; mt < 4; mt++) {
        const int row0 = bm*128 + wm*64 + mt*16 + (lane >> 2);
        #pragma unroll
        for (int nt = 0; nt < 4; nt++) {
            const int gn = bn*128 + wn*32 + nt*8 + 2*(lane & 3);
            const float b0 = bias[gn], b1 = bias[gn+1];
            float v00 = fmaxf(fmaf(acc[mt][nt][0], INV_WSCALE, b0), 0.f);
            float v01 = fmaxf(fmaf(acc[mt][nt][1], INV_WSCALE, b1), 0.f);
            float v10 = fmaxf(fmaf(acc[mt][nt][2], INV_WSCALE, b0), 0.f);
            float v11 = fmaxf(fmaf(acc[mt][nt][3], INV_WSCALE, b1), 0.f);
            if (out_f16) {
                *(uint32_t*)&Chf[(size_t)row0 * DHID + gn] =
                    pack2h(__float2half_rn(v00), __float2half_rn(v01));
                *(uint32_t*)&Chf[(size_t)(row0+8) * DHID + gn] =
                    pack2h(__float2half_rn(v10), __float2half_rn(v11));
            } else {
                *(float2*)&Cf[(size_t)row0 * DHID + gn]     = make_float2(v00, v01);
                *(float2*)&Cf[(size_t)(row0+8) * DHID + gn] = make_float2(v10, v11);
            }
        }
    }
}

// ---------------------------------------------------------------------------
// Kernel 4: heads, 8 ROIs per block.
// ---------------------------------------------------------------------------
#define HEAD_SMEM (8 * DHID * 4 + 8 * 32 * 4)

__global__ __launch_bounds__(128)
void head_kernel(const float* __restrict__ X,
                 const float* __restrict__ Wc, const float* __restrict__ bc,
                 const float* __restrict__ Wr, const float* __restrict__ br,
                 float* __restrict__ out)
{
    extern __shared__ float xs[];             // [4096][8]
    float* logits = xs + 8 * DHID;            // [8][32]
    const int b = blockIdx.x, t = threadIdx.x;

    for (int idx = t; idx < 8 * DHID; idx += 128) {
        int r = idx >> 12, k = idx & (DHID - 1);
        xs[k * 8 + r] = X[(size_t)(b * 8 + r) * DHID + k];
    }
    __syncthreads();

    if (t < NCLS + NREG) {
        const bool is_cls = (t < NCLS);
        const float* W = is_cls ? Wc : Wr;
        const int nc   = is_cls ? NCLS : NREG;
        const int j    = is_cls ? t : (t - NCLS);
        const float bv = is_cls ? bc[j] : br[j];
        float acc[8];
        #pragma unroll
        for (int r = 0; r < 8; r++) acc[r] = bv;
        #pragma unroll 4
        for (int k = 0; k < DHID; k++) {
            float w = W[(size_t)k * nc + j];
            float4 a = *(float4*)&xs[k * 8];
            float4 bq = *(float4*)&xs[k * 8 + 4];
            acc[0] = fmaf(a.x,  w, acc[0]);
            acc[1] = fmaf(a.y,  w, acc[1]);
            acc[2] = fmaf(a.z,  w, acc[2]);
            acc[3] = fmaf(a.w,  w, acc[3]);
            acc[4] = fmaf(bq.x, w, acc[4]);
            acc[5] = fmaf(bq.y, w, acc[5]);
            acc[6] = fmaf(bq.z, w, acc[6]);
            acc[7] = fmaf(bq.w, w, acc[7]);
        }
        if (is_cls) {
            #pragma unroll
            for (int r = 0; r < 8; r++) logits[r * 32 + j] = acc[r];
        } else {
            #pragma unroll
            for (int r = 0; r < 8; r++)
                out[(size_t)N_ROI * NCLS + (size_t)(b * 8 + r) * NREG + j] = acc[r];
        }
    }
    __syncthreads();

    if (t < 8) {
        int roi = b * 8 + t;
        float m = logits[t * 32];
        #pragma unroll
        for (int j = 1; j < NCLS; j++) m = fmaxf(m, logits[t * 32 + j]);
        float e[NCLS], s = 0.f;
        #pragma unroll
        for (int j = 0; j < NCLS; j++) { e[j] = expf(logits[t * 32 + j] - m); s += e[j]; }
        float inv = 1.0f / s;
        #pragma unroll
        for (int j = 0; j < NCLS; j++) out[(size_t)roi * NCLS + j] = e[j] * inv;
    }
}

// ---------------------------------------------------------------------------
// Launch
// ---------------------------------------------------------------------------
extern "C" void kernel_launch(void* const* d_in, const int* in_sizes, int n_in,
                              void* d_out, int out_size)
{
    const float* feats = (const float*)d_in[0];
    const float* props = (const float*)d_in[1];
    const float* W1    = (const float*)d_in[2];
    const float* b1    = (const float*)d_in[3];
    const float* W2    = (const float*)d_in[4];
    const float* b2    = (const float*)d_in[5];
    const float* Wc    = (const float*)d_in[6];
    const float* bc    = (const float*)d_in[7];
    const float* Wr    = (const float*)d_in[8];
    const float* br    = (const float*)d_in[9];
    float* out = (float*)d_out;

    __half *x0, *x1, *w1, *w2;
    float *x2;
    cudaGetSymbolAddress((void**)&x0, g_x0);
    cudaGetSymbolAddress((void**)&x1, g_x1);
    cudaGetSymbolAddress((void**)&x2, g_x2);
    cudaGetSymbolAddress((void**)&w1, g_w1);
    cudaGetSymbolAddress((void**)&w2, g_w2);

    cudaFuncSetAttribute(gemm_tc_kernel, cudaFuncAttributeMaxDynamicSharedMemorySize, GEMM_SMEM);
    cudaFuncSetAttribute(head_kernel,    cudaFuncAttributeMaxDynamicSharedMemorySize, HEAD_SMEM);

    // 1. ROI crop_and_resize + maxpool -> x0 fp16
    roi_pool_kernel<<<dim3(N_ROI, POOL), 128>>>(feats, props, x0);

    // 2. Weight convert+transpose -> fp16*1024 K-major
    convert_w_kernel<<<dim3(DHID / 32, DFLAT / 64), 256>>>(W1, w1, DFLAT, DHID);
    convert_w_kernel<<<dim3(DHID / 32, DHID  / 64), 256>>>(W2, w2, DHID,  DHID);

    // 3. FC1 -> x1 fp16
    gemm_tc_kernel<<<dim3(DHID / 128, M_PAD / 128), 256, GEMM_SMEM>>>(
        x0, N_ROI, w1, b1, nullptr, x1, DFLAT, 1);

    // 4. FC2 -> x2 fp32
    gemm_tc_kernel<<<dim3(DHID / 128, M_PAD / 128), 256, GEMM_SMEM>>>(
        x1, M_PAD, w2, b2, x2, nullptr, DHID, 0);

    // 5. Heads
    head_kernel<<<N_ROI / 8, 128, HEAD_SMEM>>>(x2, Wc, bc, Wr, br, out);
}

// round 14
// speedup vs baseline: 3.2431x; 1.3772x over previous
#include <cuda_runtime.h>
#include <cuda_bf16.h>
#include <cuda_fp16.h>
#include <math.h>
#include <stdint.h>

// ---------------------------------------------------------------------------
// Problem constants
// ---------------------------------------------------------------------------
#define N_ROI   1000
#define M_PAD   1024
#define FH      38
#define FW      50
#define FCH     512
#define CROP    14
#define POOL    7
#define DFLAT   25088
#define DHID    4096
#define NCLS    21
#define NREG    80
#define NHEAD   128                 // padded head output width

#define WSCALE     1024.0f          // weight pre-scale (2^10)
#define INV_WSCALE (1.0f/1024.0f)

// ---------------------------------------------------------------------------
// Scratch (device globals — no allocation allowed)
// ---------------------------------------------------------------------------
__device__ __half g_x0 [(size_t)M_PAD * DFLAT];      // pooled feats, fp16
__device__ __half g_x1 [(size_t)M_PAD * DHID];       // FC1 out, fp16
__device__ __half g_x2 [(size_t)M_PAD * DHID];       // FC2 out, fp16
__device__ float  g_hd [(size_t)M_PAD * NHEAD];      // head GEMM out, fp32
__device__ __half g_w1 [(size_t)DHID * DFLAT];       // W1^T * 1024 fp16
__device__ __half g_w2 [(size_t)DHID * DHID];        // W2^T * 1024 fp16
__device__ __half g_whd[(size_t)NHEAD * DHID];       // [Wc|Wr|0]^T * 1024 fp16
__device__ float  g_bhd[NHEAD];                      // combined head bias

// ---------------------------------------------------------------------------
// asm helpers (compute_103-safe)
// ---------------------------------------------------------------------------
__device__ __forceinline__ uint32_t smem_u32(const void* p) {
    uint32_t a;
    asm("{ .reg .u64 t; cvta.to.shared.u64 t, %1; cvt.u32.u64 %0, t; }" : "=r"(a) : "l"(p));
    return a;
}
__device__ __forceinline__ void ldsm4(uint32_t r[4], uint32_t addr) {
    asm volatile("ldmatrix.sync.aligned.m8n8.x4.shared.b16 {%0,%1,%2,%3}, [%4];"
                 : "=r"(r[0]), "=r"(r[1]), "=r"(r[2]), "=r"(r[3]) : "r"(addr));
}
__device__ __forceinline__ void mma16816(float d[4], const uint32_t a[4],
                                         uint32_t b0, uint32_t b1) {
    asm volatile(
        "mma.sync.aligned.m16n8k16.row.col.f32.f16.f16.f32 "
        "{%0,%1,%2,%3}, {%4,%5,%6,%7}, {%8,%9}, {%0,%1,%2,%3};"
        : "+f"(d[0]), "+f"(d[1]), "+f"(d[2]), "+f"(d[3])
        : "r"(a[0]), "r"(a[1]), "r"(a[2]), "r"(a[3]), "r"(b0), "r"(b1));
}
#define CP_A16(dst, src) \
    asm volatile("cp.async.cg.shared.global [%0], [%1], 16;" :: "r"(dst), "l"(src))
#define CP_A16Z(dst, src, n) \
    asm volatile("cp.async.cg.shared.global [%0], [%1], 16, %2;" :: "r"(dst), "l"(src), "r"(n))
#define CP_COMMIT()      asm volatile("cp.async.commit_group;" ::: "memory")
#define CP_WAIT_GROUP(n) asm volatile("cp.async.wait_group %0;" :: "n"(n) : "memory")

__device__ __forceinline__ uint32_t pack2h(__half a, __half b) {
    __half2 t; t.x = a; t.y = b;
    return *(uint32_t*)&t;
}

// 64B-row swizzle: 16B chunk index XORed with (row>>1)&3. Conflict-free.
__device__ __forceinline__ uint32_t sw_off(int row, int chunk) {
    return (uint32_t)(row * 64 + ((chunk ^ ((row >> 1) & 3)) << 4));
}

// ---------------------------------------------------------------------------
// Kernel 1: crop_and_resize + 2x2 maxpool, emits fp16 directly.
// ---------------------------------------------------------------------------
__global__ __launch_bounds__(128)
void roi_pool_kernel(const float* __restrict__ feats,
                     const float* __restrict__ props,
                     __half* __restrict__ x0)
{
    const int n  = blockIdx.x;
    const int py = blockIdx.y;
    const int c4 = threadIdx.x;

    const float y1 = props[n*4 + 0];
    const float x1 = props[n*4 + 1];
    const float y2 = props[n*4 + 2];
    const float x2 = props[n*4 + 3];

    const float Hm1 = (float)(FH - 1);
    const float Wm1 = (float)(FW - 1);
    const float ystep = (y2 - y1) * Hm1 * (1.0f / (CROP - 1));
    const float xstep = (x2 - x1) * Wm1 * (1.0f / (CROP - 1));
    const float ybase = y1 * Hm1;
    const float xbase = x1 * Wm1;

    int   y0i[2], y1i[2];
    float wy[2];
    #pragma unroll
    for (int dy = 0; dy < 2; dy++) {
        float ys = ybase + (float)(2*py + dy) * ystep;
        float yf = floorf(ys);
        wy[dy] = ys - yf;
        int yi = (int)yf;
        if (yi < 0) yi = 0;
        if (yi > FH-1) yi = FH-1;
        y0i[dy] = yi;
        y1i[dy] = (yi + 1 < FH-1) ? (yi + 1) : (FH-1);
    }

    for (int px = 0; px < POOL; px++) {
        float4 mx = make_float4(-1e30f, -1e30f, -1e30f, -1e30f);
        #pragma unroll
        for (int dx = 0; dx < 2; dx++) {
            float xs = xbase + (float)(2*px + dx) * xstep;
            float xf = floorf(xs);
            float wx = xs - xf;
            int xi = (int)xf;
            if (xi < 0) xi = 0;
            if (xi > FW-1) xi = FW-1;
            int x0c = xi;
            int x1c = (xi + 1 < FW-1) ? (xi + 1) : (FW-1);
            #pragma unroll
            for (int dy = 0; dy < 2; dy++) {
                const float4* r0 = (const float4*)&feats[((size_t)y0i[dy]*FW)*FCH];
                const float4* r1 = (const float4*)&feats[((size_t)y1i[dy]*FW)*FCH];
                float4 v00 = r0[(size_t)x0c*(FCH/4) + c4];
                float4 v01 = r0[(size_t)x1c*(FCH/4) + c4];
                float4 v10 = r1[(size_t)x0c*(FCH/4) + c4];
                float4 v11 = r1[(size_t)x1c*(FCH/4) + c4];
                float w = wy[dy];
                float4 top, bot, val;
                top.x = v00.x + (v01.x - v00.x) * wx;
                top.y = v00.y + (v01.y - v00.y) * wx;
                top.z = v00.z + (v01.z - v00.z) * wx;
                top.w = v00.w + (v01.w - v00.w) * wx;
                bot.x = v10.x + (v11.x - v10.x) * wx;
                bot.y = v10.y + (v11.y - v10.y) * wx;
                bot.z = v10.z + (v11.z - v10.z) * wx;
                bot.w = v10.w + (v11.w - v10.w) * wx;
                val.x = top.x + (bot.x - top.x) * w;
                val.y = top.y + (bot.y - top.y) * w;
                val.z = top.z + (bot.z - top.z) * w;
                val.w = top.w + (bot.w - top.w) * w;
                mx.x = fmaxf(mx.x, val.x);
                mx.y = fmaxf(mx.y, val.y);
                mx.z = fmaxf(mx.z, val.z);
                mx.w = fmaxf(mx.w, val.w);
            }
        }
        size_t idx = (size_t)n*DFLAT + ((size_t)(py*POOL + px))*FCH + (size_t)c4*4;
        *(uint2*)&x0[idx] = make_uint2(
            pack2h(__float2half_rn(mx.x), __float2half_rn(mx.y)),
            pack2h(__float2half_rn(mx.z), __float2half_rn(mx.w)));
    }
}

// ---------------------------------------------------------------------------
// Kernel 2: W [K,N] fp32 -> W^T*1024 [N,K] fp16 (single plane).
// ---------------------------------------------------------------------------
__global__ __launch_bounds__(256)
void convert_w_kernel(const float* __restrict__ W,
                      __half* __restrict__ T,
                      int K, int N)
{
    __shared__ float ts[64][33];
    const int tx = threadIdx.x & 31;
    const int ty = threadIdx.x >> 5;
    const int kb = blockIdx.y * 64;
    const int nb = blockIdx.x * 32;

    #pragma unroll
    for (int j = 0; j < 8; j++) {
        int r = ty + j * 8;
        ts[r][tx] = W[(size_t)(kb + r) * N + nb + tx];
    }
    __syncthreads();

    #pragma unroll
    for (int j = 0; j < 4; j++) {
        int n = ty + j * 8;
        float a = ts[2*tx][n]     * WSCALE;
        float b = ts[2*tx + 1][n] * WSCALE;
        size_t o = (size_t)(nb + n) * K + kb + 2 * tx;
        *(uint32_t*)&T[o] = pack2h(__float2half_rn(a), __float2half_rn(b));
    }
}

// ---------------------------------------------------------------------------
// Kernel 2b: build combined head weights [128][4096] fp16*1024 + bias.
// grid (128, 16), block 256.
// ---------------------------------------------------------------------------
__global__ __launch_bounds__(256)
void convert_head_kernel(const float* __restrict__ Wc, const float* __restrict__ bc,
                         const float* __restrict__ Wr, const float* __restrict__ br,
                         __half* __restrict__ T, float* __restrict__ bias)
{
    const int j = blockIdx.x;                       // head col 0..127
    const int k = blockIdx.y * 256 + threadIdx.x;   // 0..4095
    float v = 0.0f;
    if (j < NCLS)                 v = Wc[(size_t)k * NCLS + j];
    else if (j < NCLS + NREG)     v = Wr[(size_t)k * NREG + (j - NCLS)];
    T[(size_t)j * DHID + k] = __float2half_rn(v * WSCALE);

    if (blockIdx.y == 0 && threadIdx.x == 0) {
        float bv = 0.0f;
        if (j < NCLS)             bv = bc[j];
        else if (j < NCLS + NREG) bv = br[j - NCLS];
        bias[j] = bv;
    }
}

// ---------------------------------------------------------------------------
// Kernel 3: HMMA fp16 single-product GEMM.
// D = act((A @ B^T) * 2^-10 + bias); A fp16, B = W^T*1024 fp16.
// BM=128, BN=128, BK=32, 256 threads, warp tile 64x32, 5-stage cp.async,
// 64B swizzled rows, 2 CTAs/SM.
// ---------------------------------------------------------------------------
#define A_S 0
#define B_S 8192
#define STAGE  16384
#define NSTAGE 5
#define GEMM_SMEM (NSTAGE * STAGE)     // 81920 B -> 2 CTAs/SM

__global__ __launch_bounds__(256, 2)
void gemm_tc_kernel(const __half* __restrict__ A,
                    int m_real,
                    const __half* __restrict__ B,
                    const float* __restrict__ bias,
                    float* __restrict__ Cf,
                    __half* __restrict__ Chf,
                    int K, int ldc, int out_f16, int do_relu)
{
    extern __shared__ char smem[];
    const uint32_t sb0 = smem_u32(smem);
    const int tid  = threadIdx.x;
    const int wid  = tid >> 5;
    const int lane = tid & 31;
    const int wm   = wid & 1;            // 0..1 (M groups of 64)
    const int wn   = wid >> 1;           // 0..3 (N groups of 32)
    const int bn = blockIdx.x, bm = blockIdx.y;
    const int nch = K >> 5;

    // ---- load roles: rows lr and lr+64, 16B chunk lc ----
    const int lr = tid >> 2;             // 0..63
    const int lc = tid & 3;
    uint32_t a_fill[2]; const __half *as[2], *bs[2];
    uint32_t dofs[2];
    #pragma unroll
    for (int p = 0; p < 2; p++) {
        int row = lr + p * 64;
        int gm  = bm * 128 + row;
        a_fill[p] = (gm < m_real) ? 16u : 0u;
        int sr = (gm < m_real) ? gm : (m_real - 1);
        as[p] = A + (size_t)sr * K + lc * 8;
        bs[p] = B + (size_t)(bn * 128 + row) * K + lc * 8;
        dofs[p] = sw_off(row, lc);
    }

    float acc[4][4][4];
    #pragma unroll
    for (int i = 0; i < 4; i++)
        #pragma unroll
        for (int j = 0; j < 4; j++)
            #pragma unroll
            for (int e = 0; e < 4; e++) acc[i][j][e] = 0.0f;

    // ---- prologue: stages 0..3 ----
    #pragma unroll
    for (int s = 0; s < 4; s++) {
        if (s < nch) {
            const uint32_t st = sb0 + (uint32_t)s * STAGE;
            const int k0 = s * 32;
            #pragma unroll
            for (int p = 0; p < 2; p++) {
                CP_A16Z(st + A_S + dofs[p], as[p] + k0, a_fill[p]);
                CP_A16(st + B_S + dofs[p], bs[p] + k0);
            }
        }
        CP_COMMIT();
    }

    for (int c = 0; c < nch; c++) {
        const uint32_t st = sb0 + (uint32_t)(c % NSTAGE) * STAGE;
        CP_WAIT_GROUP(3);
        __syncthreads();

        if (c + 4 < nch) {
            const uint32_t sn = sb0 + (uint32_t)((c + 4) % NSTAGE) * STAGE;
            const int k0 = (c + 4) * 32;
            #pragma unroll
            for (int p = 0; p < 2; p++) {
                CP_A16Z(sn + A_S + dofs[p], as[p] + k0, a_fill[p]);
                CP_A16(sn + B_S + dofs[p], bs[p] + k0);
            }
        }
        CP_COMMIT();

        #pragma unroll
        for (int kk = 0; kk < 2; kk++) {
            const int chunk = kk * 2 + (lane >> 4);
            const int lrow  = lane & 15;
            uint32_t q[2][4];
            #pragma unroll
            for (int nt2 = 0; nt2 < 2; nt2++) {
                int r = wn*32 + nt2*16 + lrow;
                ldsm4(q[nt2], st + B_S + sw_off(r, chunk));
            }
            uint32_t a4[4][4];
            #pragma unroll
            for (int mt = 0; mt < 4; mt++) {
                int r = wm*64 + mt*16 + lrow;
                ldsm4(a4[mt], st + A_S + sw_off(r, chunk));
            }
            #pragma unroll
            for (int mt = 0; mt < 4; mt++)
                #pragma unroll
                for (int nt2 = 0; nt2 < 2; nt2++) {
                    mma16816(acc[mt][2*nt2],   a4[mt], q[nt2][0], q[nt2][2]);
                    mma16816(acc[mt][2*nt2+1], a4[mt], q[nt2][1], q[nt2][3]);
                }
        }
    }

    // ---- epilogue: descale + bias (+relu) ----
    #pragma unroll
    for (int mt = 0; mt < 4; mt++) {
        const int row0 = bm*128 + wm*64 + mt*16 + (lane >> 2);
        #pragma unroll
        for (int nt = 0; nt < 4; nt++) {
            const int gn = bn*128 + wn*32 + nt*8 + 2*(lane & 3);
            const float b0 = bias[gn], b1 = bias[gn+1];
            float v00 = fmaf(acc[mt][nt][0], INV_WSCALE, b0);
            float v01 = fmaf(acc[mt][nt][1], INV_WSCALE, b1);
            float v10 = fmaf(acc[mt][nt][2], INV_WSCALE, b0);
            float v11 = fmaf(acc[mt][nt][3], INV_WSCALE, b1);
            if (do_relu) {
                v00 = fmaxf(v00, 0.f); v01 = fmaxf(v01, 0.f);
                v10 = fmaxf(v10, 0.f); v11 = fmaxf(v11, 0.f);
            }
            if (out_f16) {
                *(uint32_t*)&Chf[(size_t)row0 * ldc + gn] =
                    pack2h(__float2half_rn(v00), __float2half_rn(v01));
                *(uint32_t*)&Chf[(size_t)(row0+8) * ldc + gn] =
                    pack2h(__float2half_rn(v10), __float2half_rn(v11));
            } else {
                *(float2*)&Cf[(size_t)row0 * ldc + gn]     = make_float2(v00, v01);
                *(float2*)&Cf[(size_t)(row0+8) * ldc + gn] = make_float2(v10, v11);
            }
        }
    }
}

// ---------------------------------------------------------------------------
// Kernel 4: head postprocess — softmax(cls) + copy(reg). 1 thread per ROI.
// ---------------------------------------------------------------------------
__global__ __launch_bounds__(128)
void head_post_kernel(const float* __restrict__ hd, float* __restrict__ out)
{
    const int r = blockIdx.x * 128 + threadIdx.x;
    if (r >= N_ROI) return;
    const float* row = hd + (size_t)r * NHEAD;

    float m = row[0];
    #pragma unroll
    for (int j = 1; j < NCLS; j++) m = fmaxf(m, row[j]);
    float e[NCLS], s = 0.f;
    #pragma unroll
    for (int j = 0; j < NCLS; j++) { e[j] = expf(row[j] - m); s += e[j]; }
    float inv = 1.0f / s;
    #pragma unroll
    for (int j = 0; j < NCLS; j++) out[(size_t)r * NCLS + j] = e[j] * inv;

    #pragma unroll
    for (int j = 0; j < NREG; j++)
        out[(size_t)N_ROI * NCLS + (size_t)r * NREG + j] = row[NCLS + j];
}

// ---------------------------------------------------------------------------
// Launch
// ---------------------------------------------------------------------------
extern "C" void kernel_launch(void* const* d_in, const int* in_sizes, int n_in,
                              void* d_out, int out_size)
{
    const float* feats = (const float*)d_in[0];
    const float* props = (const float*)d_in[1];
    const float* W1    = (const float*)d_in[2];
    const float* b1    = (const float*)d_in[3];
    const float* W2    = (const float*)d_in[4];
    const float* b2    = (const float*)d_in[5];
    const float* Wc    = (const float*)d_in[6];
    const float* bc    = (const float*)d_in[7];
    const float* Wr    = (const float*)d_in[8];
    const float* br    = (const float*)d_in[9];
    float* out = (float*)d_out;

    __half *x0, *x1, *x2, *w1, *w2, *whd;
    float *hd, *bhd;
    cudaGetSymbolAddress((void**)&x0,  g_x0);
    cudaGetSymbolAddress((void**)&x1,  g_x1);
    cudaGetSymbolAddress((void**)&x2,  g_x2);
    cudaGetSymbolAddress((void**)&hd,  g_hd);
    cudaGetSymbolAddress((void**)&w1,  g_w1);
    cudaGetSymbolAddress((void**)&w2,  g_w2);
    cudaGetSymbolAddress((void**)&whd, g_whd);
    cudaGetSymbolAddress((void**)&bhd, g_bhd);

    cudaFuncSetAttribute(gemm_tc_kernel, cudaFuncAttributeMaxDynamicSharedMemorySize, GEMM_SMEM);

    // 1. ROI crop_and_resize + maxpool -> x0 fp16
    roi_pool_kernel<<<dim3(N_ROI, POOL), 128>>>(feats, props, x0);

    // 2. Weight convert+transpose -> fp16*1024 K-major
    convert_w_kernel<<<dim3(DHID / 32, DFLAT / 64), 256>>>(W1, w1, DFLAT, DHID);
    convert_w_kernel<<<dim3(DHID / 32, DHID  / 64), 256>>>(W2, w2, DHID,  DHID);
    convert_head_kernel<<<dim3(NHEAD, DHID / 256), 256>>>(Wc, bc, Wr, br, whd, bhd);

    // 3. FC1 -> x1 fp16 (relu)
    gemm_tc_kernel<<<dim3(DHID / 128, M_PAD / 128), 256, GEMM_SMEM>>>(
        x0, N_ROI, w1, b1, nullptr, x1, DFLAT, DHID, 1, 1);

    // 4. FC2 -> x2 fp16 (relu)
    gemm_tc_kernel<<<dim3(DHID / 128, M_PAD / 128), 256, GEMM_SMEM>>>(
        x1, M_PAD, w2, b2, nullptr, x2, DHID, DHID, 1, 1);

    // 5. Head GEMM -> hd fp32 [1024 x 128] (no relu)
    gemm_tc_kernel<<<dim3(1, M_PAD / 128), 256, GEMM_SMEM>>>(
        x2, M_PAD, whd, bhd, hd, nullptr, DHID, NHEAD, 0, 0);

    // 6. Softmax + scatter
    head_post_kernel<<<(N_ROI + 127) / 128, 128>>>(hd, out);
}

// round 15
// speedup vs baseline: 3.2553x; 1.0038x over previous
#include <cuda_runtime.h>
#include <cuda_bf16.h>
#include <cuda_fp16.h>
#include <math.h>
#include <stdint.h>

// ---------------------------------------------------------------------------
// Problem constants
// ---------------------------------------------------------------------------
#define N_ROI   1000
#define M_PAD   1024
#define FH      38
#define FW      50
#define FCH     512
#define CROP    14
#define POOL    7
#define DFLAT   25088
#define DHID    4096
#define NCLS    21
#define NREG    80
#define NHEAD   128                 // padded head output width

#define WSCALE     1024.0f          // weight pre-scale (2^10)
#define INV_WSCALE (1.0f/1024.0f)

// ---------------------------------------------------------------------------
// Scratch (device globals — no allocation allowed)
// ---------------------------------------------------------------------------
__device__ __half g_x0 [(size_t)M_PAD * DFLAT];      // pooled feats, fp16
__device__ __half g_x1 [(size_t)M_PAD * DHID];       // FC1 out, fp16
__device__ __half g_x2 [(size_t)M_PAD * DHID];       // FC2 out, fp16
__device__ float  g_hd [(size_t)M_PAD * NHEAD];      // head GEMM out, fp32
__device__ __half g_w1 [(size_t)DHID * DFLAT];       // W1^T * 1024 fp16
__device__ __half g_w2 [(size_t)DHID * DHID];        // W2^T * 1024 fp16
__device__ __half g_whd[(size_t)NHEAD * DHID];       // [Wc|Wr|0]^T * 1024 fp16
__device__ float  g_bhd[NHEAD];                      // combined head bias

// ---------------------------------------------------------------------------
// asm helpers (compute_103-safe)
// ---------------------------------------------------------------------------
__device__ __forceinline__ uint32_t smem_u32(const void* p) {
    uint32_t a;
    asm("{ .reg .u64 t; cvta.to.shared.u64 t, %1; cvt.u32.u64 %0, t; }" : "=r"(a) : "l"(p));
    return a;
}
__device__ __forceinline__ void ldsm4(uint32_t r[4], uint32_t addr) {
    asm volatile("ldmatrix.sync.aligned.m8n8.x4.shared.b16 {%0,%1,%2,%3}, [%4];"
                 : "=r"(r[0]), "=r"(r[1]), "=r"(r[2]), "=r"(r[3]) : "r"(addr));
}
__device__ __forceinline__ void mma16816(float d[4], const uint32_t a[4],
                                         uint32_t b0, uint32_t b1) {
    asm volatile(
        "mma.sync.aligned.m16n8k16.row.col.f32.f16.f16.f32 "
        "{%0,%1,%2,%3}, {%4,%5,%6,%7}, {%8,%9}, {%0,%1,%2,%3};"
        : "+f"(d[0]), "+f"(d[1]), "+f"(d[2]), "+f"(d[3])
        : "r"(a[0]), "r"(a[1]), "r"(a[2]), "r"(a[3]), "r"(b0), "r"(b1));
}
#define CP_A16(dst, src) \
    asm volatile("cp.async.cg.shared.global [%0], [%1], 16;" :: "r"(dst), "l"(src))
#define CP_A16Z(dst, src, n) \
    asm volatile("cp.async.cg.shared.global [%0], [%1], 16, %2;" :: "r"(dst), "l"(src), "r"(n))
#define CP_COMMIT()      asm volatile("cp.async.commit_group;" ::: "memory")
#define CP_WAIT_GROUP(n) asm volatile("cp.async.wait_group %0;" :: "n"(n) : "memory")

__device__ __forceinline__ uint32_t pack2h(__half a, __half b) {
    __half2 t; t.x = a; t.y = b;
    return *(uint32_t*)&t;
}

// 64B-row swizzle: 16B chunk index XORed with (row>>1)&3. Conflict-free.
__device__ __forceinline__ uint32_t sw_off(int row, int chunk) {
    return (uint32_t)(row * 64 + ((chunk ^ ((row >> 1) & 3)) << 4));
}

// ---------------------------------------------------------------------------
// Kernel 1: crop_and_resize + 2x2 maxpool, emits fp16 directly.
// ---------------------------------------------------------------------------
__global__ __launch_bounds__(128)
void roi_pool_kernel(const float* __restrict__ feats,
                     const float* __restrict__ props,
                     __half* __restrict__ x0)
{
    const int n  = blockIdx.x;
    const int py = blockIdx.y;
    const int c4 = threadIdx.x;

    const float y1 = props[n*4 + 0];
    const float x1 = props[n*4 + 1];
    const float y2 = props[n*4 + 2];
    const float x2 = props[n*4 + 3];

    const float Hm1 = (float)(FH - 1);
    const float Wm1 = (float)(FW - 1);
    const float ystep = (y2 - y1) * Hm1 * (1.0f / (CROP - 1));
    const float xstep = (x2 - x1) * Wm1 * (1.0f / (CROP - 1));
    const float ybase = y1 * Hm1;
    const float xbase = x1 * Wm1;

    int   y0i[2], y1i[2];
    float wy[2];
    #pragma unroll
    for (int dy = 0; dy < 2; dy++) {
        float ys = ybase + (float)(2*py + dy) * ystep;
        float yf = floorf(ys);
        wy[dy] = ys - yf;
        int yi = (int)yf;
        if (yi < 0) yi = 0;
        if (yi > FH-1) yi = FH-1;
        y0i[dy] = yi;
        y1i[dy] = (yi + 1 < FH-1) ? (yi + 1) : (FH-1);
    }

    for (int px = 0; px < POOL; px++) {
        float4 mx = make_float4(-1e30f, -1e30f, -1e30f, -1e30f);
        #pragma unroll
        for (int dx = 0; dx < 2; dx++) {
            float xs = xbase + (float)(2*px + dx) * xstep;
            float xf = floorf(xs);
            float wx = xs - xf;
            int xi = (int)xf;
            if (xi < 0) xi = 0;
            if (xi > FW-1) xi = FW-1;
            int x0c = xi;
            int x1c = (xi + 1 < FW-1) ? (xi + 1) : (FW-1);
            #pragma unroll
            for (int dy = 0; dy < 2; dy++) {
                const float4* r0 = (const float4*)&feats[((size_t)y0i[dy]*FW)*FCH];
                const float4* r1 = (const float4*)&feats[((size_t)y1i[dy]*FW)*FCH];
                float4 v00 = r0[(size_t)x0c*(FCH/4) + c4];
                float4 v01 = r0[(size_t)x1c*(FCH/4) + c4];
                float4 v10 = r1[(size_t)x0c*(FCH/4) + c4];
                float4 v11 = r1[(size_t)x1c*(FCH/4) + c4];
                float w = wy[dy];
                float4 top, bot, val;
                top.x = v00.x + (v01.x - v00.x) * wx;
                top.y = v00.y + (v01.y - v00.y) * wx;
                top.z = v00.z + (v01.z - v00.z) * wx;
                top.w = v00.w + (v01.w - v00.w) * wx;
                bot.x = v10.x + (v11.x - v10.x) * wx;
                bot.y = v10.y + (v11.y - v10.y) * wx;
                bot.z = v10.z + (v11.z - v10.z) * wx;
                bot.w = v10.w + (v11.w - v10.w) * wx;
                val.x = top.x + (bot.x - top.x) * w;
                val.y = top.y + (bot.y - top.y) * w;
                val.z = top.z + (bot.z - top.z) * w;
                val.w = top.w + (bot.w - top.w) * w;
                mx.x = fmaxf(mx.x, val.x);
                mx.y = fmaxf(mx.y, val.y);
                mx.z = fmaxf(mx.z, val.z);
                mx.w = fmaxf(mx.w, val.w);
            }
        }
        size_t idx = (size_t)n*DFLAT + ((size_t)(py*POOL + px))*FCH + (size_t)c4*4;
        *(uint2*)&x0[idx] = make_uint2(
            pack2h(__float2half_rn(mx.x), __float2half_rn(mx.y)),
            pack2h(__float2half_rn(mx.z), __float2half_rn(mx.w)));
    }
}

// ---------------------------------------------------------------------------
// Kernel 2: W [K,N] fp32 -> W^T*1024 [N,K] fp16.
// Tile 128K x 32N per block; writes 256B contiguous segments per warp-row.
// ---------------------------------------------------------------------------
__global__ __launch_bounds__(256)
void convert_w_kernel(const float* __restrict__ W,
                      __half* __restrict__ T,
                      int K, int N)
{
    __shared__ float ts[128][33];
    const int tx = threadIdx.x & 31;
    const int ty = threadIdx.x >> 5;       // 0..7
    const int kb = blockIdx.y * 128;
    const int nb = blockIdx.x * 32;

    #pragma unroll
    for (int j = 0; j < 16; j++) {
        int r = ty + j * 8;                // 0..127
        ts[r][tx] = W[(size_t)(kb + r) * N + nb + tx];
    }
    __syncthreads();

    #pragma unroll
    for (int j = 0; j < 4; j++) {
        int n = ty + j * 8;                // 0..31
        float a0 = ts[4*tx + 0][n] * WSCALE;
        float a1 = ts[4*tx + 1][n] * WSCALE;
        float a2 = ts[4*tx + 2][n] * WSCALE;
        float a3 = ts[4*tx + 3][n] * WSCALE;
        size_t o = (size_t)(nb + n) * K + kb + 4 * tx;
        *(uint2*)&T[o] = make_uint2(
            pack2h(__float2half_rn(a0), __float2half_rn(a1)),
            pack2h(__float2half_rn(a2), __float2half_rn(a3)));
    }
}

// ---------------------------------------------------------------------------
// Kernel 2b: build combined head weights [128][4096] fp16*1024 + bias.
// grid (128, 16), block 256.
// ---------------------------------------------------------------------------
__global__ __launch_bounds__(256)
void convert_head_kernel(const float* __restrict__ Wc, const float* __restrict__ bc,
                         const float* __restrict__ Wr, const float* __restrict__ br,
                         __half* __restrict__ T, float* __restrict__ bias)
{
    const int j = blockIdx.x;                       // head col 0..127
    const int k = blockIdx.y * 256 + threadIdx.x;   // 0..4095
    float v = 0.0f;
    if (j < NCLS)                 v = Wc[(size_t)k * NCLS + j];
    else if (j < NCLS + NREG)     v = Wr[(size_t)k * NREG + (j - NCLS)];
    T[(size_t)j * DHID + k] = __float2half_rn(v * WSCALE);

    if (blockIdx.y == 0 && threadIdx.x == 0) {
        float bv = 0.0f;
        if (j < NCLS)             bv = bc[j];
        else if (j < NCLS + NREG) bv = br[j - NCLS];
        bias[j] = bv;
    }
}

// ---------------------------------------------------------------------------
// Kernel 3: HMMA fp16 single-product GEMM.
// D = act((A @ B^T) * 2^-10 + bias); A fp16, B = W^T*1024 fp16.
// BM=128, BN=128, BK=32, 256 threads, warp tile 64x32, 6-stage cp.async,
// 64B swizzled rows, 2 CTAs/SM.
// ---------------------------------------------------------------------------
#define A_S 0
#define B_S 8192
#define STAGE  16384
#define NSTAGE 6
#define GEMM_SMEM (NSTAGE * STAGE)     // 98304 B -> 2 CTAs/SM (192KB of 228KB)

__global__ __launch_bounds__(256, 2)
void gemm_tc_kernel(const __half* __restrict__ A,
                    int m_real,
                    const __half* __restrict__ B,
                    const float* __restrict__ bias,
                    float* __restrict__ Cf,
                    __half* __restrict__ Chf,
                    int K, int ldc, int out_f16, int do_relu)
{
    extern __shared__ char smem[];
    const uint32_t sb0 = smem_u32(smem);
    const int tid  = threadIdx.x;
    const int wid  = tid >> 5;
    const int lane = tid & 31;
    const int wm   = wid & 1;            // 0..1 (M groups of 64)
    const int wn   = wid >> 1;           // 0..3 (N groups of 32)
    const int bn = blockIdx.x, bm = blockIdx.y;
    const int nch = K >> 5;

    // ---- load roles: rows lr and lr+64, 16B chunk lc ----
    const int lr = tid >> 2;             // 0..63
    const int lc = tid & 3;
    uint32_t a_fill[2]; const __half *as[2], *bs[2];
    uint32_t dofs[2];
    #pragma unroll
    for (int p = 0; p < 2; p++) {
        int row = lr + p * 64;
        int gm  = bm * 128 + row;
        a_fill[p] = (gm < m_real) ? 16u : 0u;
        int sr = (gm < m_real) ? gm : (m_real - 1);
        as[p] = A + (size_t)sr * K + lc * 8;
        bs[p] = B + (size_t)(bn * 128 + row) * K + lc * 8;
        dofs[p] = sw_off(row, lc);
    }

    float acc[4][4][4];
    #pragma unroll
    for (int i = 0; i < 4; i++)
        #pragma unroll
        for (int j = 0; j < 4; j++)
            #pragma unroll
            for (int e = 0; e < 4; e++) acc[i][j][e] = 0.0f;

    // ---- prologue: stages 0..4 ----
    #pragma unroll
    for (int s = 0; s < 5; s++) {
        if (s < nch) {
            const uint32_t st = sb0 + (uint32_t)s * STAGE;
            const int k0 = s * 32;
            #pragma unroll
            for (int p = 0; p < 2; p++) {
                CP_A16Z(st + A_S + dofs[p], as[p] + k0, a_fill[p]);
                CP_A16(st + B_S + dofs[p], bs[p] + k0);
            }
        }
        CP_COMMIT();
    }

    for (int c = 0; c < nch; c++) {
        const uint32_t st = sb0 + (uint32_t)(c % NSTAGE) * STAGE;
        CP_WAIT_GROUP(4);
        __syncthreads();

        if (c + 5 < nch) {
            const uint32_t sn = sb0 + (uint32_t)((c + 5) % NSTAGE) * STAGE;
            const int k0 = (c + 5) * 32;
            #pragma unroll
            for (int p = 0; p < 2; p++) {
                CP_A16Z(sn + A_S + dofs[p], as[p] + k0, a_fill[p]);
                CP_A16(sn + B_S + dofs[p], bs[p] + k0);
            }
        }
        CP_COMMIT();

        #pragma unroll
        for (int kk = 0; kk < 2; kk++) {
            const int chunk = kk * 2 + (lane >> 4);
            const int lrow  = lane & 15;
            uint32_t q[2][4];
            #pragma unroll
            for (int nt2 = 0; nt2 < 2; nt2++) {
                int r = wn*32 + nt2*16 + lrow;
                ldsm4(q[nt2], st + B_S + sw_off(r, chunk));
            }
            uint32_t a4[4][4];
            #pragma unroll
            for (int mt = 0; mt < 4; mt++) {
                int r = wm*64 + mt*16 + lrow;
                ldsm4(a4[mt], st + A_S + sw_off(r, chunk));
            }
            #pragma unroll
            for (int mt = 0; mt < 4; mt++)
                #pragma unroll
                for (int nt2 = 0; nt2 < 2; nt2++) {
                    mma16816(acc[mt][2*nt2],   a4[mt], q[nt2][0], q[nt2][2]);
                    mma16816(acc[mt][2*nt2+1], a4[mt], q[nt2][1], q[nt2][3]);
                }
        }
    }

    // ---- epilogue: descale + bias (+relu) ----
    #pragma unroll
    for (int mt = 0; mt < 4; mt++) {
        const int row0 = bm*128 + wm*64 + mt*16 + (lane >> 2);
        #pragma unroll
        for (int nt = 0; nt < 4; nt++) {
            const int gn = bn*128 + wn*32 + nt*8 + 2*(lane & 3);
            const float b0 = bias[gn], b1 = bias[gn+1];
            float v00 = fmaf(acc[mt][nt][0], INV_WSCALE, b0);
            float v01 = fmaf(acc[mt][nt][1], INV_WSCALE, b1);
            float v10 = fmaf(acc[mt][nt][2], INV_WSCALE, b0);
            float v11 = fmaf(acc[mt][nt][3], INV_WSCALE, b1);
            if (do_relu) {
                v00 = fmaxf(v00, 0.f); v01 = fmaxf(v01, 0.f);
                v10 = fmaxf(v10, 0.f); v11 = fmaxf(v11, 0.f);
            }
            if (out_f16) {
                *(uint32_t*)&Chf[(size_t)row0 * ldc + gn] =
                    pack2h(__float2half_rn(v00), __float2half_rn(v01));
                *(uint32_t*)&Chf[(size_t)(row0+8) * ldc + gn] =
                    pack2h(__float2half_rn(v10), __float2half_rn(v11));
            } else {
                *(float2*)&Cf[(size_t)row0 * ldc + gn]     = make_float2(v00, v01);
                *(float2*)&Cf[(size_t)(row0+8) * ldc + gn] = make_float2(v10, v11);
            }
        }
    }
}

// ---------------------------------------------------------------------------
// Kernel 4: head postprocess — softmax(cls) + copy(reg). 1 thread per ROI.
// ---------------------------------------------------------------------------
__global__ __launch_bounds__(128)
void head_post_kernel(const float* __restrict__ hd, float* __restrict__ out)
{
    const int r = blockIdx.x * 128 + threadIdx.x;
    if (r >= N_ROI) return;
    const float* row = hd + (size_t)r * NHEAD;

    float m = row[0];
    #pragma unroll
    for (int j = 1; j < NCLS; j++) m = fmaxf(m, row[j]);
    float e[NCLS], s = 0.f;
    #pragma unroll
    for (int j = 0; j < NCLS; j++) { e[j] = expf(row[j] - m); s += e[j]; }
    float inv = 1.0f / s;
    #pragma unroll
    for (int j = 0; j < NCLS; j++) out[(size_t)r * NCLS + j] = e[j] * inv;

    #pragma unroll
    for (int j = 0; j < NREG; j++)
        out[(size_t)N_ROI * NCLS + (size_t)r * NREG + j] = row[NCLS + j];
}

// ---------------------------------------------------------------------------
// Launch
// ---------------------------------------------------------------------------
extern "C" void kernel_launch(void* const* d_in, const int* in_sizes, int n_in,
                              void* d_out, int out_size)
{
    const float* feats = (const float*)d_in[0];
    const float* props = (const float*)d_in[1];
    const float* W1    = (const float*)d_in[2];
    const float* b1    = (const float*)d_in[3];
    const float* W2    = (const float*)d_in[4];
    const float* b2    = (const float*)d_in[5];
    const float* Wc    = (const float*)d_in[6];
    const float* bc    = (const float*)d_in[7];
    const float* Wr    = (const float*)d_in[8];
    const float* br    = (const float*)d_in[9];
    float* out = (float*)d_out;

    __half *x0, *x1, *x2, *w1, *w2, *whd;
    float *hd, *bhd;
    cudaGetSymbolAddress((void**)&x0,  g_x0);
    cudaGetSymbolAddress((void**)&x1,  g_x1);
    cudaGetSymbolAddress((void**)&x2,  g_x2);
    cudaGetSymbolAddress((void**)&hd,  g_hd);
    cudaGetSymbolAddress((void**)&w1,  g_w1);
    cudaGetSymbolAddress((void**)&w2,  g_w2);
    cudaGetSymbolAddress((void**)&whd, g_whd);
    cudaGetSymbolAddress((void**)&bhd, g_bhd);

    cudaFuncSetAttribute(gemm_tc_kernel, cudaFuncAttributeMaxDynamicSharedMemorySize, GEMM_SMEM);

    // 1. ROI crop_and_resize + maxpool -> x0 fp16
    roi_pool_kernel<<<dim3(N_ROI, POOL), 128>>>(feats, props, x0);

    // 2. Weight convert+transpose -> fp16*1024 K-major
    convert_w_kernel<<<dim3(DHID / 32, DFLAT / 128), 256>>>(W1, w1, DFLAT, DHID);
    convert_w_kernel<<<dim3(DHID / 32, DHID  / 128), 256>>>(W2, w2, DHID,  DHID);
    convert_head_kernel<<<dim3(NHEAD, DHID / 256), 256>>>(Wc, bc, Wr, br, whd, bhd);

    // 3. FC1 -> x1 fp16 (relu)
    gemm_tc_kernel<<<dim3(DHID / 128, M_PAD / 128), 256, GEMM_SMEM>>>(
        x0, N_ROI, w1, b1, nullptr, x1, DFLAT, DHID, 1, 1);

    // 4. FC2 -> x2 fp16 (relu)
    gemm_tc_kernel<<<dim3(DHID / 128, M_PAD / 128), 256, GEMM_SMEM>>>(
        x1, M_PAD, w2, b2, nullptr, x2, DHID, DHID, 1, 1);

    // 5. Head GEMM -> hd fp32 [1024 x 128] (no relu)
    gemm_tc_kernel<<<dim3(1, M_PAD / 128), 256, GEMM_SMEM>>>(
        x2, M_PAD, whd, bhd, hd, nullptr, DHID, NHEAD, 0, 0);

    // 6. Softmax + scatter
    head_post_kernel<<<(N_ROI + 127) / 128, 128>>>(hd, out);
}